// round 1
// baseline (speedup 1.0000x reference)
#include <cuda_runtime.h>
#include <math.h>
#include <stdint.h>

#define D_MODEL 1024
#define N_HEAD  16
#define HD      64
#define T_LEN   512
#define S_LEN   1024
#define BATCH   16
#define MQ      (T_LEN * BATCH)   /* 8192  query rows  */
#define MKV     (S_LEN * BATCH)   /* 16384 kv rows     */

// ---------------- scratch (static device globals; no allocation) ------------
__device__ float g_h  [MQ  * D_MODEL];        // LN output        32 MB
__device__ float g_qkv[MQ  * 3 * D_MODEL];    // self QKV / cross Q  96 MB
__device__ float g_kv [MKV * 2 * D_MODEL];    // cross K,V       128 MB
__device__ float g_ctx[MQ  * D_MODEL];        // attention ctx    32 MB
__device__ float g_ffn[MQ  * 4 * D_MODEL];    // MLP hidden      128 MB

// ---------------- LayerNorm: one block per row, D=1024 ----------------------
__global__ __launch_bounds__(256) void ln_kernel(
    const float* __restrict__ x, const float* __restrict__ g,
    const float* __restrict__ b, float* __restrict__ y)
{
    int row = blockIdx.x;
    const float4* xr = (const float4*)(x + (size_t)row * D_MODEL);
    float4*       yr = (float4*)      (y + (size_t)row * D_MODEL);
    int tid = threadIdx.x;                       // 256 threads * float4 = 1024
    float4 v = xr[tid];
    float s  = v.x + v.y + v.z + v.w;
    float ss = v.x*v.x + v.y*v.y + v.z*v.z + v.w*v.w;
    #pragma unroll
    for (int o = 16; o; o >>= 1) {
        s  += __shfl_xor_sync(~0u, s,  o);
        ss += __shfl_xor_sync(~0u, ss, o);
    }
    __shared__ float smS[8], smSS[8];
    int w = tid >> 5;
    if ((tid & 31) == 0) { smS[w] = s; smSS[w] = ss; }
    __syncthreads();
    if (tid < 32) {
        s  = (tid < 8) ? smS[tid]  : 0.f;
        ss = (tid < 8) ? smSS[tid] : 0.f;
        #pragma unroll
        for (int o = 4; o; o >>= 1) {
            s  += __shfl_xor_sync(~0u, s,  o);
            ss += __shfl_xor_sync(~0u, ss, o);
        }
        if (tid == 0) { smS[0] = s; smSS[0] = ss; }
    }
    __syncthreads();
    float mean = smS[0] * (1.f / D_MODEL);
    float var  = smSS[0] * (1.f / D_MODEL) - mean * mean;
    float rstd = rsqrtf(var + 1e-5f);
    float4 gv = ((const float4*)g)[tid];
    float4 bv = ((const float4*)b)[tid];
    float4 o;
    o.x = (v.x - mean) * rstd * gv.x + bv.x;
    o.y = (v.y - mean) * rstd * gv.y + bv.y;
    o.z = (v.z - mean) * rstd * gv.z + bv.z;
    o.w = (v.w - mean) * rstd * gv.w + bv.w;
    yr[tid] = o;
}

// ---------------- SGEMM-NT: C[M,N] = A[M,K] @ W[N,K]^T + bias (+res)(+gelu) --
// BM=BN=128, BK=8, 256 threads, 8x8 microtile. M,N % 128 == 0, K % 8 == 0.
__global__ __launch_bounds__(256) void sgemm_nt(
    const float* __restrict__ A, const float* __restrict__ W,
    const float* __restrict__ bias, const float* res,
    float* C, int M, int N, int K, int act)
{
    __shared__ float As[8][128];
    __shared__ float Bs[8][128];
    int tid = threadIdx.x;
    int tx = tid & 15, ty = tid >> 4;
    int m0 = blockIdx.y * 128, n0 = blockIdx.x * 128;
    int lrow = tid >> 1, lcol = (tid & 1) * 4;
    const float* Aload = A + (size_t)(m0 + lrow) * K + lcol;
    const float* Wload = W + (size_t)(n0 + lrow) * K + lcol;

    float acc[8][8];
    #pragma unroll
    for (int i = 0; i < 8; i++)
        #pragma unroll
        for (int j = 0; j < 8; j++) acc[i][j] = 0.f;

    for (int kt = 0; kt < K; kt += 8) {
        float4 a = *(const float4*)(Aload + kt);
        float4 w = *(const float4*)(Wload + kt);
        As[lcol + 0][lrow] = a.x; As[lcol + 1][lrow] = a.y;
        As[lcol + 2][lrow] = a.z; As[lcol + 3][lrow] = a.w;
        Bs[lcol + 0][lrow] = w.x; Bs[lcol + 1][lrow] = w.y;
        Bs[lcol + 2][lrow] = w.z; Bs[lcol + 3][lrow] = w.w;
        __syncthreads();
        #pragma unroll
        for (int kk = 0; kk < 8; kk++) {
            float ar[8], br[8];
            *(float4*)&ar[0] = *(const float4*)&As[kk][ty * 8];
            *(float4*)&ar[4] = *(const float4*)&As[kk][ty * 8 + 4];
            *(float4*)&br[0] = *(const float4*)&Bs[kk][tx * 8];
            *(float4*)&br[4] = *(const float4*)&Bs[kk][tx * 8 + 4];
            #pragma unroll
            for (int i = 0; i < 8; i++)
                #pragma unroll
                for (int j = 0; j < 8; j++)
                    acc[i][j] += ar[i] * br[j];
        }
        __syncthreads();
    }

    #pragma unroll
    for (int i = 0; i < 8; i++) {
        int m = m0 + ty * 8 + i;
        #pragma unroll
        for (int j = 0; j < 8; j++) {
            int n = n0 + tx * 8 + j;
            float vv = acc[i][j] + bias[n];
            if (res) vv += res[(size_t)m * N + n];
            if (act) vv = vv / (1.f + __expf(-1.702f * vv));   // quick_gelu
            C[(size_t)m * N + n] = vv;
        }
    }
}

// ---------------- attention: block = (b*H+h, t-tile of 8 rows) ---------------
// q row (t,b): q[((t*B+b)*q_ld) + h*64 + d]; ctx written [T,B,D] compact.
__global__ __launch_bounds__(256) void attn_kernel(
    const float* __restrict__ q, int q_ld,
    const float* __restrict__ k, int k_ld,
    const float* __restrict__ v, int v_ld,
    float* __restrict__ ctx,
    int S, float scale)
{
    const int TQ = 8;
    extern __shared__ float sm[];
    float* q_s = sm;                    // TQ*64
    float* ks  = q_s + TQ * 64;         // 32*65 (padded)
    float* red = ks + 32 * 65;          // 4*64
    float* inv = red + 4 * 64;          // TQ
    float* sc  = inv + TQ;              // TQ*S

    int bh = blockIdx.x;
    int b  = bh / N_HEAD;
    int hh = bh % N_HEAD;
    int t0 = blockIdx.y * TQ;
    int tid = threadIdx.x;

    // load q tile, pre-scaled
    for (int i = tid; i < TQ * 64; i += 256) {
        int ti = i >> 6, d = i & 63;
        q_s[i] = q[(size_t)((t0 + ti) * BATCH + b) * q_ld + hh * 64 + d] * scale;
    }
    __syncthreads();

    // pass 1: scores
    {
        int ti = tid >> 5, sr = tid & 31;
        for (int s0 = 0; s0 < S; s0 += 32) {
            for (int i = tid; i < 32 * 64; i += 256) {
                int r = i >> 6, d = i & 63;
                ks[r * 65 + d] =
                    k[(size_t)((s0 + r) * BATCH + b) * k_ld + hh * 64 + d];
            }
            __syncthreads();
            float acc = 0.f;
            #pragma unroll
            for (int d = 0; d < 64; d++)
                acc += q_s[ti * 64 + d] * ks[sr * 65 + d];
            sc[ti * S + s0 + sr] = acc;
            __syncthreads();
        }
    }

    // softmax: one warp per query row
    {
        int ti = tid >> 5, lane = tid & 31;
        float m = -1e30f;
        for (int s = lane; s < S; s += 32) m = fmaxf(m, sc[ti * S + s]);
        #pragma unroll
        for (int o = 16; o; o >>= 1) m = fmaxf(m, __shfl_xor_sync(~0u, m, o));
        float sum = 0.f;
        for (int s = lane; s < S; s += 32) {
            float e = __expf(sc[ti * S + s] - m);
            sc[ti * S + s] = e;
            sum += e;
        }
        #pragma unroll
        for (int o = 16; o; o >>= 1) sum += __shfl_xor_sync(~0u, sum, o);
        if (lane == 0) inv[ti] = 1.f / sum;
    }
    __syncthreads();

    // pass 2: ctx = P @ V
    {
        int d = tid & 63, ch = tid >> 6;        // 4 s-chunks
        float acc[TQ];
        #pragma unroll
        for (int i = 0; i < TQ; i++) acc[i] = 0.f;
        for (int s = ch; s < S; s += 4) {
            float vv = v[(size_t)(s * BATCH + b) * v_ld + hh * 64 + d];
            #pragma unroll
            for (int ti = 0; ti < TQ; ti++) acc[ti] += sc[ti * S + s] * vv;
        }
        #pragma unroll
        for (int ti = 0; ti < TQ; ti++) {
            red[ch * 64 + d] = acc[ti];
            __syncthreads();
            if (tid < 64) {
                float r = red[d] + red[64 + d] + red[128 + d] + red[192 + d];
                ctx[(size_t)((t0 + ti) * BATCH + b) * D_MODEL + hh * 64 + d] =
                    r * inv[ti];
            }
            __syncthreads();
        }
    }
}

// ---------------- orchestration ---------------------------------------------
extern "C" void kernel_launch(void* const* d_in, const int* in_sizes, int n_in,
                              void* d_out, int out_size)
{
    const float* x        = (const float*)d_in[0];
    const float* hid      = (const float*)d_in[1];
    const float* ln1_g    = (const float*)d_in[2];
    const float* ln1_b    = (const float*)d_in[3];
    const float* sa_in_w  = (const float*)d_in[4];
    const float* sa_in_b  = (const float*)d_in[5];
    const float* sa_out_w = (const float*)d_in[6];
    const float* sa_out_b = (const float*)d_in[7];
    const float* ln2_g    = (const float*)d_in[8];
    const float* ln2_b    = (const float*)d_in[9];
    const float* ca_in_w  = (const float*)d_in[10];
    const float* ca_in_b  = (const float*)d_in[11];
    const float* ca_out_w = (const float*)d_in[12];
    const float* ca_out_b = (const float*)d_in[13];
    const float* ln3_g    = (const float*)d_in[14];
    const float* ln3_b    = (const float*)d_in[15];
    const float* fc_w     = (const float*)d_in[16];
    const float* fc_b     = (const float*)d_in[17];
    const float* proj_w   = (const float*)d_in[18];
    const float* proj_b   = (const float*)d_in[19];
    float* out = (float*)d_out;

    float *h, *qkv, *kv, *ctx, *ffn;
    cudaGetSymbolAddress((void**)&h,   g_h);
    cudaGetSymbolAddress((void**)&qkv, g_qkv);
    cudaGetSymbolAddress((void**)&kv,  g_kv);
    cudaGetSymbolAddress((void**)&ctx, g_ctx);
    cudaGetSymbolAddress((void**)&ffn, g_ffn);

    const float scale = 0.125f;   // 1/sqrt(64)
    size_t shm_attn_self  = (size_t)(8*64 + 32*65 + 4*64 + 8 + 8*T_LEN) * 4;
    size_t shm_attn_cross = (size_t)(8*64 + 32*65 + 4*64 + 8 + 8*S_LEN) * 4;

    // ---- self attention ----
    ln_kernel<<<MQ, 256>>>(x, ln1_g, ln1_b, h);
    sgemm_nt<<<dim3(3 * D_MODEL / 128, MQ / 128), 256>>>(
        h, sa_in_w, sa_in_b, nullptr, qkv, MQ, 3 * D_MODEL, D_MODEL, 0);
    attn_kernel<<<dim3(BATCH * N_HEAD, T_LEN / 8), 256, shm_attn_self>>>(
        qkv, 3 * D_MODEL,
        qkv + D_MODEL, 3 * D_MODEL,
        qkv + 2 * D_MODEL, 3 * D_MODEL,
        ctx, T_LEN, scale);
    sgemm_nt<<<dim3(D_MODEL / 128, MQ / 128), 256>>>(
        ctx, sa_out_w, sa_out_b, x, out, MQ, D_MODEL, D_MODEL, 0);

    // ---- cross attention ----
    ln_kernel<<<MQ, 256>>>(out, ln2_g, ln2_b, h);
    sgemm_nt<<<dim3(D_MODEL / 128, MQ / 128), 256>>>(
        h, ca_in_w, ca_in_b, nullptr, qkv, MQ, D_MODEL, D_MODEL, 0);
    sgemm_nt<<<dim3(2 * D_MODEL / 128, MKV / 128), 256>>>(
        hid, ca_in_w + (size_t)D_MODEL * D_MODEL, ca_in_b + D_MODEL,
        nullptr, kv, MKV, 2 * D_MODEL, D_MODEL, 0);
    attn_kernel<<<dim3(BATCH * N_HEAD, T_LEN / 8), 256, shm_attn_cross>>>(
        qkv, D_MODEL,
        kv, 2 * D_MODEL,
        kv + D_MODEL, 2 * D_MODEL,
        ctx, S_LEN, scale);
    sgemm_nt<<<dim3(D_MODEL / 128, MQ / 128), 256>>>(
        ctx, ca_out_w, ca_out_b, out, out, MQ, D_MODEL, D_MODEL, 0);

    // ---- MLP ----
    ln_kernel<<<MQ, 256>>>(out, ln3_g, ln3_b, h);
    sgemm_nt<<<dim3(4 * D_MODEL / 128, MQ / 128), 256>>>(
        h, fc_w, fc_b, nullptr, ffn, MQ, 4 * D_MODEL, D_MODEL, 1);
    sgemm_nt<<<dim3(D_MODEL / 128, MQ / 128), 256>>>(
        ffn, proj_w, proj_b, out, out, MQ, D_MODEL, 4 * D_MODEL, 0);
}

// round 3
// speedup vs baseline: 1.6088x; 1.6088x over previous
#include <cuda_runtime.h>
#include <cuda_bf16.h>
#include <math.h>
#include <stdint.h>

#define D_MODEL 1024
#define N_HEAD  16
#define T_LEN   512
#define S_LEN   1024
#define BATCH   16
#define MQ      (T_LEN * BATCH)   /* 8192  query rows  */
#define MKV     (S_LEN * BATCH)   /* 16384 kv rows     */

// ---------------- scratch (static device globals; no allocation) ------------
__device__ float g_h  [MQ  * D_MODEL];
__device__ float g_qkv[MQ  * 3 * D_MODEL];
__device__ float g_kv [MKV * 2 * D_MODEL];
__device__ float g_ctx[MQ  * D_MODEL];
__device__ float g_ffn[MQ  * 4 * D_MODEL];

__device__ __forceinline__ uint32_t b2u(__nv_bfloat162 x) {
    return *reinterpret_cast<uint32_t*>(&x);
}

// mma.sync m16n8k16 bf16 (sm_80+; no 'a' arch feature needed)
__device__ __forceinline__ void mma_bf16(float* c, const uint32_t* a,
                                         const uint32_t* b) {
    asm volatile(
        "mma.sync.aligned.m16n8k16.row.col.f32.bf16.bf16.f32 "
        "{%0,%1,%2,%3}, {%4,%5,%6,%7}, {%8,%9}, {%0,%1,%2,%3};"
        : "+f"(c[0]), "+f"(c[1]), "+f"(c[2]), "+f"(c[3])
        : "r"(a[0]), "r"(a[1]), "r"(a[2]), "r"(a[3]),
          "r"(b[0]), "r"(b[1]));
}

// ======================= tensor-core GEMM ===================================
// C[M,N] = A[M,K] @ W[N,K]^T + bias (+res)(+quickGELU), fp32 in/out.
// bf16 hi/lo split (3 passes). Tile 128x128, BK=32, 8 warps (4x2), 32KB smem.
// Smem layout is "fragment order": A plane: [ks][mtile(8)][lane(32)][4xb32]
//                                  B plane: [ks][ntile(16)][lane(32)][2xb32]
__global__ __launch_bounds__(256, 2) void gemm_tc(
    const float* __restrict__ A, const float* __restrict__ W,
    const float* __restrict__ bias, const float* res,
    float* __restrict__ C, int M, int N, int K, int act)
{
    __shared__ char smem[32768];
    char* AH = smem;            // 8KB
    char* AL = smem + 8192;     // 8KB
    char* BH = smem + 16384;    // 8KB
    char* BL = smem + 24576;    // 8KB

    const int tid  = threadIdx.x;
    const int wid  = tid >> 5, lane = tid & 31;
    const int wm   = wid >> 1, wn = wid & 1;      // 4x2 warp grid
    const int m0   = blockIdx.y * 128, n0 = blockIdx.x * 128;

    float acc[2][8][4];
    #pragma unroll
    for (int i = 0; i < 2; i++)
        #pragma unroll
        for (int j = 0; j < 8; j++)
            #pragma unroll
            for (int q = 0; q < 4; q++) acc[i][j][q] = 0.f;

    const int nCh = K >> 5;
    for (int c = 0; c < nCh; c++) {
        if (c) __syncthreads();
        const int k0 = c << 5;
        // ---- load + split + store (fragment-ordered) ----
        #pragma unroll
        for (int it = 0; it < 8; it++) {
            int j = tid + (it << 8);      // 0..2047
            int m = j >> 4;               // 0..127 (row of A / row of W)
            int cc2 = (j & 15) << 1;      // even k within chunk: 0,2,..30
            int ks = cc2 >> 4;            // k-step 0/1
            int cc = cc2 & 15;            // k within step

            // A
            float2 av = *(const float2*)(A + (size_t)(m0 + m) * K + k0 + cc2);
            __nv_bfloat162 h = __floats2bfloat162_rn(av.x, av.y);
            float2 hf = __bfloat1622float2(h);
            __nv_bfloat162 l = __floats2bfloat162_rn(av.x - hf.x, av.y - hf.y);
            int regA  = ((m & 15) >= 8 ? 1 : 0) + (cc >= 8 ? 2 : 0);
            int laneA = (m & 7) * 4 + ((cc & 7) >> 1);
            uint32_t offA = (uint32_t)(((ks * 8 + (m >> 4)) * 32 + laneA) * 16
                                       + regA * 4);
            *(uint32_t*)(AH + offA) = b2u(h);
            *(uint32_t*)(AL + offA) = b2u(l);

            // B (W row n = B column n, k-major -> ".col" operand)
            float2 wv = *(const float2*)(W + (size_t)(n0 + m) * K + k0 + cc2);
            __nv_bfloat162 hb = __floats2bfloat162_rn(wv.x, wv.y);
            float2 hbf = __bfloat1622float2(hb);
            __nv_bfloat162 lb = __floats2bfloat162_rn(wv.x - hbf.x, wv.y - hbf.y);
            int regB  = (cc >= 8) ? 1 : 0;
            int laneB = (m & 7) * 4 + ((cc & 7) >> 1);
            uint32_t offB = (uint32_t)(((ks * 16 + (m >> 3)) * 32 + laneB) * 8
                                       + regB * 4);
            *(uint32_t*)(BH + offB) = b2u(hb);
            *(uint32_t*)(BL + offB) = b2u(lb);
        }
        __syncthreads();

        // ---- compute ----
        #pragma unroll
        for (int ks = 0; ks < 2; ks++) {
            uint32_t aH[2][4], aL[2][4];
            #pragma unroll
            for (int mt = 0; mt < 2; mt++) {
                uint32_t o = ((ks * 8 + wm * 2 + mt) * 32 + lane) * 16;
                *(uint4*)aH[mt] = *(const uint4*)(AH + o);
                *(uint4*)aL[mt] = *(const uint4*)(AL + o);
            }
            #pragma unroll
            for (int nt = 0; nt < 8; nt++) {
                uint32_t o = ((ks * 16 + wn * 8 + nt) * 32 + lane) * 8;
                uint32_t bH[2], bL[2];
                *(uint2*)bH = *(const uint2*)(BH + o);
                *(uint2*)bL = *(const uint2*)(BL + o);
                mma_bf16(acc[0][nt], aH[0], bH);
                mma_bf16(acc[1][nt], aH[1], bH);
                mma_bf16(acc[0][nt], aH[0], bL);
                mma_bf16(acc[1][nt], aH[1], bL);
                mma_bf16(acc[0][nt], aL[0], bH);
                mma_bf16(acc[1][nt], aL[1], bH);
            }
        }
    }

    // ---- epilogue: fuse bias / residual / quickGELU ----
    const int r0 = m0 + wm * 32 + (lane >> 2);
    const int c0 = n0 + wn * 64 + (lane & 3) * 2;
    #pragma unroll
    for (int mt = 0; mt < 2; mt++) {
        #pragma unroll
        for (int nt = 0; nt < 8; nt++) {
            int col = c0 + nt * 8;
            float2 bv = *(const float2*)(bias + col);
            #pragma unroll
            for (int hrow = 0; hrow < 2; hrow++) {
                int row = r0 + mt * 16 + hrow * 8;
                float2 vv;
                vv.x = acc[mt][nt][hrow * 2 + 0] + bv.x;
                vv.y = acc[mt][nt][hrow * 2 + 1] + bv.y;
                size_t goff = (size_t)row * N + col;
                if (res) {
                    float2 rr = *(const float2*)(res + goff);
                    vv.x += rr.x; vv.y += rr.y;
                }
                if (act) {
                    vv.x = vv.x / (1.f + __expf(-1.702f * vv.x));
                    vv.y = vv.y / (1.f + __expf(-1.702f * vv.y));
                }
                *(float2*)(C + goff) = vv;
            }
        }
    }
}

// ---------------- LayerNorm: one block per row, D=1024 ----------------------
__global__ __launch_bounds__(256) void ln_kernel(
    const float* __restrict__ x, const float* __restrict__ g,
    const float* __restrict__ b, float* __restrict__ y)
{
    int row = blockIdx.x;
    const float4* xr = (const float4*)(x + (size_t)row * D_MODEL);
    float4*       yr = (float4*)      (y + (size_t)row * D_MODEL);
    int tid = threadIdx.x;
    float4 v = xr[tid];
    float s  = v.x + v.y + v.z + v.w;
    float ss = v.x*v.x + v.y*v.y + v.z*v.z + v.w*v.w;
    #pragma unroll
    for (int o = 16; o; o >>= 1) {
        s  += __shfl_xor_sync(~0u, s,  o);
        ss += __shfl_xor_sync(~0u, ss, o);
    }
    __shared__ float smS[8], smSS[8];
    int w = tid >> 5;
    if ((tid & 31) == 0) { smS[w] = s; smSS[w] = ss; }
    __syncthreads();
    if (tid < 32) {
        s  = (tid < 8) ? smS[tid]  : 0.f;
        ss = (tid < 8) ? smSS[tid] : 0.f;
        #pragma unroll
        for (int o = 4; o; o >>= 1) {
            s  += __shfl_xor_sync(~0u, s,  o);
            ss += __shfl_xor_sync(~0u, ss, o);
        }
        if (tid == 0) { smS[0] = s; smSS[0] = ss; }
    }
    __syncthreads();
    float mean = smS[0] * (1.f / D_MODEL);
    float var  = smSS[0] * (1.f / D_MODEL) - mean * mean;
    float rstd = rsqrtf(var + 1e-5f);
    float4 gv = ((const float4*)g)[tid];
    float4 bv = ((const float4*)b)[tid];
    float4 o;
    o.x = (v.x - mean) * rstd * gv.x + bv.x;
    o.y = (v.y - mean) * rstd * gv.y + bv.y;
    o.z = (v.z - mean) * rstd * gv.z + bv.z;
    o.w = (v.w - mean) * rstd * gv.w + bv.w;
    yr[tid] = o;
}

// ---------------- attention: block = (b*H+h, t-tile of 8 rows) ---------------
__global__ __launch_bounds__(256) void attn_kernel(
    const float* __restrict__ q, int q_ld,
    const float* __restrict__ k, int k_ld,
    const float* __restrict__ v, int v_ld,
    float* __restrict__ ctx,
    int S, float scale)
{
    const int TQ = 8;
    extern __shared__ float sm[];
    float* q_s = sm;
    float* ks  = q_s + TQ * 64;
    float* red = ks + 32 * 65;
    float* inv = red + 4 * 64;
    float* sc  = inv + TQ;

    int bh = blockIdx.x;
    int b  = bh / N_HEAD;
    int hh = bh % N_HEAD;
    int t0 = blockIdx.y * TQ;
    int tid = threadIdx.x;

    for (int i = tid; i < TQ * 64; i += 256) {
        int ti = i >> 6, d = i & 63;
        q_s[i] = q[(size_t)((t0 + ti) * BATCH + b) * q_ld + hh * 64 + d] * scale;
    }
    __syncthreads();

    {
        int ti = tid >> 5, sr = tid & 31;
        for (int s0 = 0; s0 < S; s0 += 32) {
            for (int i = tid; i < 32 * 64; i += 256) {
                int r = i >> 6, d = i & 63;
                ks[r * 65 + d] =
                    k[(size_t)((s0 + r) * BATCH + b) * k_ld + hh * 64 + d];
            }
            __syncthreads();
            float acc = 0.f;
            #pragma unroll
            for (int d = 0; d < 64; d++)
                acc += q_s[ti * 64 + d] * ks[sr * 65 + d];
            sc[ti * S + s0 + sr] = acc;
            __syncthreads();
        }
    }

    {
        int ti = tid >> 5, lane = tid & 31;
        float m = -1e30f;
        for (int s = lane; s < S; s += 32) m = fmaxf(m, sc[ti * S + s]);
        #pragma unroll
        for (int o = 16; o; o >>= 1) m = fmaxf(m, __shfl_xor_sync(~0u, m, o));
        float sum = 0.f;
        for (int s = lane; s < S; s += 32) {
            float e = __expf(sc[ti * S + s] - m);
            sc[ti * S + s] = e;
            sum += e;
        }
        #pragma unroll
        for (int o = 16; o; o >>= 1) sum += __shfl_xor_sync(~0u, sum, o);
        if (lane == 0) inv[ti] = 1.f / sum;
    }
    __syncthreads();

    {
        int d = tid & 63, ch = tid >> 6;
        float acc[TQ];
        #pragma unroll
        for (int i = 0; i < TQ; i++) acc[i] = 0.f;
        for (int s = ch; s < S; s += 4) {
            float vv = v[(size_t)(s * BATCH + b) * v_ld + hh * 64 + d];
            #pragma unroll
            for (int ti = 0; ti < TQ; ti++) acc[ti] += sc[ti * S + s] * vv;
        }
        #pragma unroll
        for (int ti = 0; ti < TQ; ti++) {
            red[ch * 64 + d] = acc[ti];
            __syncthreads();
            if (tid < 64) {
                float r = red[d] + red[64 + d] + red[128 + d] + red[192 + d];
                ctx[(size_t)((t0 + ti) * BATCH + b) * D_MODEL + hh * 64 + d] =
                    r * inv[ti];
            }
            __syncthreads();
        }
    }
}

// ---------------- orchestration ---------------------------------------------
extern "C" void kernel_launch(void* const* d_in, const int* in_sizes, int n_in,
                              void* d_out, int out_size)
{
    const float* x        = (const float*)d_in[0];
    const float* hid      = (const float*)d_in[1];
    const float* ln1_g    = (const float*)d_in[2];
    const float* ln1_b    = (const float*)d_in[3];
    const float* sa_in_w  = (const float*)d_in[4];
    const float* sa_in_b  = (const float*)d_in[5];
    const float* sa_out_w = (const float*)d_in[6];
    const float* sa_out_b = (const float*)d_in[7];
    const float* ln2_g    = (const float*)d_in[8];
    const float* ln2_b    = (const float*)d_in[9];
    const float* ca_in_w  = (const float*)d_in[10];
    const float* ca_in_b  = (const float*)d_in[11];
    const float* ca_out_w = (const float*)d_in[12];
    const float* ca_out_b = (const float*)d_in[13];
    const float* ln3_g    = (const float*)d_in[14];
    const float* ln3_b    = (const float*)d_in[15];
    const float* fc_w     = (const float*)d_in[16];
    const float* fc_b     = (const float*)d_in[17];
    const float* proj_w   = (const float*)d_in[18];
    const float* proj_b   = (const float*)d_in[19];
    float* out = (float*)d_out;

    float *h, *qkv, *kv, *ctx, *ffn;
    cudaGetSymbolAddress((void**)&h,   g_h);
    cudaGetSymbolAddress((void**)&qkv, g_qkv);
    cudaGetSymbolAddress((void**)&kv,  g_kv);
    cudaGetSymbolAddress((void**)&ctx, g_ctx);
    cudaGetSymbolAddress((void**)&ffn, g_ffn);

    const float scale = 0.125f;
    size_t shm_attn_self  = (size_t)(8*64 + 32*65 + 4*64 + 8 + 8*T_LEN) * 4;
    size_t shm_attn_cross = (size_t)(8*64 + 32*65 + 4*64 + 8 + 8*S_LEN) * 4;

    // ---- self attention ----
    ln_kernel<<<MQ, 256>>>(x, ln1_g, ln1_b, h);
    gemm_tc<<<dim3(3 * D_MODEL / 128, MQ / 128), 256>>>(
        h, sa_in_w, sa_in_b, nullptr, qkv, MQ, 3 * D_MODEL, D_MODEL, 0);
    attn_kernel<<<dim3(BATCH * N_HEAD, T_LEN / 8), 256, shm_attn_self>>>(
        qkv, 3 * D_MODEL,
        qkv + D_MODEL, 3 * D_MODEL,
        qkv + 2 * D_MODEL, 3 * D_MODEL,
        ctx, T_LEN, scale);
    gemm_tc<<<dim3(D_MODEL / 128, MQ / 128), 256>>>(
        ctx, sa_out_w, sa_out_b, x, out, MQ, D_MODEL, D_MODEL, 0);

    // ---- cross attention ----
    ln_kernel<<<MQ, 256>>>(out, ln2_g, ln2_b, h);
    gemm_tc<<<dim3(D_MODEL / 128, MQ / 128), 256>>>(
        h, ca_in_w, ca_in_b, nullptr, qkv, MQ, D_MODEL, D_MODEL, 0);
    gemm_tc<<<dim3(2 * D_MODEL / 128, MKV / 128), 256>>>(
        hid, ca_in_w + (size_t)D_MODEL * D_MODEL, ca_in_b + D_MODEL,
        nullptr, kv, MKV, 2 * D_MODEL, D_MODEL, 0);
    attn_kernel<<<dim3(BATCH * N_HEAD, T_LEN / 8), 256, shm_attn_cross>>>(
        qkv, D_MODEL,
        kv, 2 * D_MODEL,
        kv + D_MODEL, 2 * D_MODEL,
        ctx, S_LEN, scale);
    gemm_tc<<<dim3(D_MODEL / 128, MQ / 128), 256>>>(
        ctx, ca_out_w, ca_out_b, out, out, MQ, D_MODEL, D_MODEL, 0);

    // ---- MLP ----
    ln_kernel<<<MQ, 256>>>(out, ln3_g, ln3_b, h);
    gemm_tc<<<dim3(4 * D_MODEL / 128, MQ / 128), 256>>>(
        h, fc_w, fc_b, nullptr, ffn, MQ, 4 * D_MODEL, D_MODEL, 1);
    gemm_tc<<<dim3(D_MODEL / 128, MQ / 128), 256>>>(
        ffn, proj_w, proj_b, out, out, MQ, D_MODEL, 4 * D_MODEL, 0);
}

// round 4
// speedup vs baseline: 2.4739x; 1.5377x over previous
#include <cuda_runtime.h>
#include <cuda_bf16.h>
#include <math.h>
#include <stdint.h>

#define D_MODEL 1024
#define N_HEAD  16
#define T_LEN   512
#define S_LEN   1024
#define BATCH   16
#define MQ      (T_LEN * BATCH)   /* 8192  query rows  */
#define MKV     (S_LEN * BATCH)   /* 16384 kv rows     */
typedef __nv_bfloat16 bf16;

// ---------------- scratch (static device globals; no allocation) ------------
#define WS_SA_IN  0u
#define WS_SA_OUT (3u*1024*1024)
#define WS_CA_IN  (4u*1024*1024)
#define WS_CA_OUT (7u*1024*1024)
#define WS_FC     (8u*1024*1024)
#define WS_PROJ   (12u*1024*1024)
#define WS_TOTAL  (16u*1024*1024)
__device__ bf16  g_w_hi[WS_TOTAL],        g_w_lo[WS_TOTAL];
__device__ bf16  g_hid_hi[MKV*D_MODEL],   g_hid_lo[MKV*D_MODEL];
__device__ bf16  g_h_hi[MQ*D_MODEL],      g_h_lo[MQ*D_MODEL];
__device__ bf16  g_qkv_hi[MQ*3*D_MODEL],  g_qkv_lo[MQ*3*D_MODEL];
__device__ bf16  g_kv_hi[MKV*2*D_MODEL],  g_kv_lo[MKV*2*D_MODEL];
__device__ bf16  g_vt_hi[256*64*S_LEN],   g_vt_lo[256*64*S_LEN];
__device__ float g_scores[134217728];                       // 256*512*1024
__device__ bf16  g_p_hi[134217728],       g_p_lo[134217728];
__device__ bf16  g_ctx_hi[MQ*D_MODEL],    g_ctx_lo[MQ*D_MODEL];
__device__ bf16  g_ffn_hi[MQ*4*D_MODEL],  g_ffn_lo[MQ*4*D_MODEL];

__device__ __forceinline__ uint32_t b2u(__nv_bfloat162 x) {
    return *reinterpret_cast<uint32_t*>(&x);
}

// mma.sync m16n8k16 bf16 (sm_80+)
__device__ __forceinline__ void mma_bf16(float* c, const uint32_t* a,
                                         const uint32_t* b) {
    asm volatile(
        "mma.sync.aligned.m16n8k16.row.col.f32.bf16.bf16.f32 "
        "{%0,%1,%2,%3}, {%4,%5,%6,%7}, {%8,%9}, {%0,%1,%2,%3};"
        : "+f"(c[0]), "+f"(c[1]), "+f"(c[2]), "+f"(c[3])
        : "r"(a[0]), "r"(a[1]), "r"(a[2]), "r"(a[3]),
          "r"(b[0]), "r"(b[1]));
}

// ======================= tensor-core GEMM ===================================
// C[m,n] = sum_k A[m,k]*B[n,k], A/B given as bf16 hi/lo pairs (3-pass split).
// Tile 128 x TN, BK=32, 8 warps 4x2. Fragment-ordered smem (no ldmatrix).
// Batched: z -> (b = z>>4, h = z&15); elem offsets  b*s?b + h*s?h.
template<int TN>
__global__ __launch_bounds__(256, 2) void gemm_bf16(
    const bf16* __restrict__ Ah, const bf16* __restrict__ Al,
    int lda, size_t sAb, size_t sAh,
    const bf16* __restrict__ Bh, const bf16* __restrict__ Bl,
    int ldb, size_t sBb, size_t sBh,
    const float* __restrict__ bias,
    const float* __restrict__ res,
    float* __restrict__ Cf, bf16* __restrict__ Chi, bf16* __restrict__ Clo,
    int ldc, size_t sCb, size_t sCh,
    int K, float oscale, int act)
{
    constexpr int NT     = TN / 16;     // n-subtiles per warp
    constexpr int BPLANE = TN * 64;     // bytes per B plane
    __shared__ char AHs[8192], ALs[8192];
    __shared__ char BHs[BPLANE], BLs[BPLANE];

    const int tid = threadIdx.x, wid = tid >> 5, lane = tid & 31;
    const int wm = wid >> 1, wn = wid & 1;
    const int m0 = blockIdx.y * 128, n0 = blockIdx.x * TN;
    const int zb = blockIdx.z >> 4, zh = blockIdx.z & 15;

    const bf16* pAh = Ah + (size_t)zb * sAb + (size_t)zh * sAh;
    const bf16* pAl = Al + (size_t)zb * sAb + (size_t)zh * sAh;
    const bf16* pBh = Bh + (size_t)zb * sBb + (size_t)zh * sBh;
    const bf16* pBl = Bl + (size_t)zb * sBb + (size_t)zh * sBh;

    float acc[2][NT][4];
    #pragma unroll
    for (int i = 0; i < 2; i++)
        #pragma unroll
        for (int j = 0; j < NT; j++)
            #pragma unroll
            for (int q = 0; q < 4; q++) acc[i][j][q] = 0.f;

    const int nCh = K >> 5;
    for (int c = 0; c < nCh; c++) {
        if (c) __syncthreads();
        const int k0 = c << 5;
        // ---- A loader: 128 rows x 4 octets ----
        #pragma unroll
        for (int it = 0; it < 2; it++) {
            int j = tid + (it << 8);
            int m = j >> 2, q = j & 3;
            size_t g = (size_t)(m0 + m) * lda + k0 + q * 8;
            uint4 vh = *(const uint4*)(pAh + g);
            uint4 vl = *(const uint4*)(pAl + g);
            int ks = q >> 1;
            int reg = (((m & 15) >= 8) ? 1 : 0) + ((q & 1) ? 2 : 0);
            uint32_t base = (uint32_t)(((ks * 8 + (m >> 4)) * 32 + (m & 7) * 4) * 16
                                       + reg * 4);
            *(uint32_t*)(AHs + base +  0) = vh.x;
            *(uint32_t*)(AHs + base + 16) = vh.y;
            *(uint32_t*)(AHs + base + 32) = vh.z;
            *(uint32_t*)(AHs + base + 48) = vh.w;
            *(uint32_t*)(ALs + base +  0) = vl.x;
            *(uint32_t*)(ALs + base + 16) = vl.y;
            *(uint32_t*)(ALs + base + 32) = vl.z;
            *(uint32_t*)(ALs + base + 48) = vl.w;
        }
        // ---- B loader: TN rows x 4 octets ----
        #pragma unroll
        for (int it = 0; it < TN / 64; it++) {
            int j = tid + (it << 8);
            int n = j >> 2, q = j & 3;
            size_t g = (size_t)(n0 + n) * ldb + k0 + q * 8;
            uint4 vh = *(const uint4*)(pBh + g);
            uint4 vl = *(const uint4*)(pBl + g);
            int ks = q >> 1;
            int reg = q & 1;
            uint32_t base = (uint32_t)(((ks * (TN / 8) + (n >> 3)) * 32
                                        + (n & 7) * 4) * 8 + reg * 4);
            *(uint32_t*)(BHs + base +  0) = vh.x;
            *(uint32_t*)(BHs + base +  8) = vh.y;
            *(uint32_t*)(BHs + base + 16) = vh.z;
            *(uint32_t*)(BHs + base + 24) = vh.w;
            *(uint32_t*)(BLs + base +  0) = vl.x;
            *(uint32_t*)(BLs + base +  8) = vl.y;
            *(uint32_t*)(BLs + base + 16) = vl.z;
            *(uint32_t*)(BLs + base + 24) = vl.w;
        }
        __syncthreads();

        // ---- compute ----
        #pragma unroll
        for (int ks = 0; ks < 2; ks++) {
            uint32_t aH[2][4], aL[2][4];
            #pragma unroll
            for (int mt = 0; mt < 2; mt++) {
                uint32_t o = ((ks * 8 + wm * 2 + mt) * 32 + lane) * 16;
                *(uint4*)aH[mt] = *(const uint4*)(AHs + o);
                *(uint4*)aL[mt] = *(const uint4*)(ALs + o);
            }
            #pragma unroll
            for (int nt = 0; nt < NT; nt++) {
                uint32_t o = ((ks * (TN / 8) + wn * NT + nt) * 32 + lane) * 8;
                uint32_t bH[2], bL[2];
                *(uint2*)bH = *(const uint2*)(BHs + o);
                *(uint2*)bL = *(const uint2*)(BLs + o);
                mma_bf16(acc[0][nt], aH[0], bH);
                mma_bf16(acc[1][nt], aH[1], bH);
                mma_bf16(acc[0][nt], aH[0], bL);
                mma_bf16(acc[1][nt], aH[1], bL);
                mma_bf16(acc[0][nt], aL[0], bH);
                mma_bf16(acc[1][nt], aL[1], bH);
            }
        }
    }

    // ---- epilogue ----
    const int r0 = m0 + wm * 32 + (lane >> 2);
    const int c0 = n0 + wn * (TN / 2) + (lane & 3) * 2;
    const size_t zoff = (size_t)zb * sCb + (size_t)zh * sCh;
    #pragma unroll
    for (int mt = 0; mt < 2; mt++) {
        #pragma unroll
        for (int nt = 0; nt < NT; nt++) {
            int col = c0 + nt * 8;
            float2 bv = make_float2(0.f, 0.f);
            if (bias) bv = *(const float2*)(bias + col);
            #pragma unroll
            for (int hrow = 0; hrow < 2; hrow++) {
                int row = r0 + mt * 16 + hrow * 8;
                float2 vv;
                vv.x = acc[mt][nt][hrow * 2 + 0] * oscale + bv.x;
                vv.y = acc[mt][nt][hrow * 2 + 1] * oscale + bv.y;
                size_t co = (size_t)row * ldc + col + zoff;
                if (res) {
                    float2 rr = *(const float2*)(res + co);
                    vv.x += rr.x; vv.y += rr.y;
                }
                if (act) {
                    vv.x = vv.x / (1.f + __expf(-1.702f * vv.x));
                    vv.y = vv.y / (1.f + __expf(-1.702f * vv.y));
                }
                if (Cf) {
                    *(float2*)(Cf + co) = vv;
                } else {
                    bf16 hx = __float2bfloat16(vv.x);
                    bf16 hy = __float2bfloat16(vv.y);
                    *(uint32_t*)(Chi + co) = b2u(__halves2bfloat162(hx, hy));
                    bf16 lx = __float2bfloat16(vv.x - __bfloat162float(hx));
                    bf16 ly = __float2bfloat16(vv.y - __bfloat162float(hy));
                    *(uint32_t*)(Clo + co) = b2u(__halves2bfloat162(lx, ly));
                }
            }
        }
    }
}

// ---------------- split fp32 -> bf16 hi/lo -----------------------------------
__global__ __launch_bounds__(256) void split_kernel(
    const float4* __restrict__ src, uint32_t* __restrict__ hi,
    uint32_t* __restrict__ lo)
{
    size_t i = (size_t)blockIdx.x * 256 + threadIdx.x;
    float4 v = src[i];
    __nv_bfloat162 h01 = __floats2bfloat162_rn(v.x, v.y);
    __nv_bfloat162 h23 = __floats2bfloat162_rn(v.z, v.w);
    float2 f01 = __bfloat1622float2(h01);
    float2 f23 = __bfloat1622float2(h23);
    __nv_bfloat162 l01 = __floats2bfloat162_rn(v.x - f01.x, v.y - f01.y);
    __nv_bfloat162 l23 = __floats2bfloat162_rn(v.z - f23.x, v.w - f23.y);
    hi[i * 2]     = b2u(h01);
    hi[i * 2 + 1] = b2u(h23);
    lo[i * 2]     = b2u(l01);
    lo[i * 2 + 1] = b2u(l23);
}

// ---------------- LayerNorm -> split bf16 ------------------------------------
__global__ __launch_bounds__(256) void ln_split_kernel(
    const float* __restrict__ x, const float* __restrict__ g,
    const float* __restrict__ b, bf16* __restrict__ yh, bf16* __restrict__ yl)
{
    int row = blockIdx.x;
    const float4* xr = (const float4*)(x + (size_t)row * D_MODEL);
    int tid = threadIdx.x;
    float4 v = xr[tid];
    float s  = v.x + v.y + v.z + v.w;
    float ss = v.x*v.x + v.y*v.y + v.z*v.z + v.w*v.w;
    #pragma unroll
    for (int o = 16; o; o >>= 1) {
        s  += __shfl_xor_sync(~0u, s,  o);
        ss += __shfl_xor_sync(~0u, ss, o);
    }
    __shared__ float smS[8], smSS[8];
    int w = tid >> 5;
    if ((tid & 31) == 0) { smS[w] = s; smSS[w] = ss; }
    __syncthreads();
    if (tid < 32) {
        s  = (tid < 8) ? smS[tid]  : 0.f;
        ss = (tid < 8) ? smSS[tid] : 0.f;
        #pragma unroll
        for (int o = 4; o; o >>= 1) {
            s  += __shfl_xor_sync(~0u, s,  o);
            ss += __shfl_xor_sync(~0u, ss, o);
        }
        if (tid == 0) { smS[0] = s; smSS[0] = ss; }
    }
    __syncthreads();
    float mean = smS[0] * (1.f / D_MODEL);
    float var  = smSS[0] * (1.f / D_MODEL) - mean * mean;
    float rstd = rsqrtf(var + 1e-5f);
    float4 gv = ((const float4*)g)[tid];
    float4 bv = ((const float4*)b)[tid];
    float4 o;
    o.x = (v.x - mean) * rstd * gv.x + bv.x;
    o.y = (v.y - mean) * rstd * gv.y + bv.y;
    o.z = (v.z - mean) * rstd * gv.z + bv.z;
    o.w = (v.w - mean) * rstd * gv.w + bv.w;
    __nv_bfloat162 h01 = __floats2bfloat162_rn(o.x, o.y);
    __nv_bfloat162 h23 = __floats2bfloat162_rn(o.z, o.w);
    float2 f01 = __bfloat1622float2(h01);
    float2 f23 = __bfloat1622float2(h23);
    __nv_bfloat162 l01 = __floats2bfloat162_rn(o.x - f01.x, o.y - f01.y);
    __nv_bfloat162 l23 = __floats2bfloat162_rn(o.z - f23.x, o.w - f23.y);
    uint32_t* yhr = (uint32_t*)(yh + (size_t)row * D_MODEL);
    uint32_t* ylr = (uint32_t*)(yl + (size_t)row * D_MODEL);
    yhr[tid * 2]     = b2u(h01);
    yhr[tid * 2 + 1] = b2u(h23);
    ylr[tid * 2]     = b2u(l01);
    ylr[tid * 2 + 1] = b2u(l23);
}

// ---------------- V transpose: vt[z][d][s] from kv-style layout --------------
__global__ __launch_bounds__(256) void vt_kernel(
    const bf16* __restrict__ inh, const bf16* __restrict__ inl,
    int ldin, int off,
    bf16* __restrict__ outh, bf16* __restrict__ outl, int S)
{
    int z = blockIdx.z, b = z >> 4, hh = z & 15;
    int s0 = blockIdx.x * 32;
    __shared__ uint16_t sh[32][66], sl[32][66];
    int tid = threadIdx.x;
    int d2 = (tid & 31) * 2, srow = tid >> 5;
    #pragma unroll
    for (int p = 0; p < 4; p++) {
        int s = srow + p * 8;
        size_t g = (size_t)((s0 + s) * BATCH + b) * ldin + off + hh * 64 + d2;
        uint32_t vh = *(const uint32_t*)(inh + g);
        uint32_t vl = *(const uint32_t*)(inl + g);
        sh[s][d2] = (uint16_t)(vh & 0xffff); sh[s][d2 + 1] = (uint16_t)(vh >> 16);
        sl[s][d2] = (uint16_t)(vl & 0xffff); sl[s][d2 + 1] = (uint16_t)(vl >> 16);
    }
    __syncthreads();
    size_t obase = (size_t)z * 64 * S + s0;
    uint16_t* oh = (uint16_t*)outh;
    uint16_t* ol = (uint16_t*)outl;
    #pragma unroll
    for (int p = 0; p < 8; p++) {
        int d = (tid >> 5) + p * 8;
        int s = tid & 31;
        oh[obase + (size_t)d * S + s] = sh[s][d];
        ol[obase + (size_t)d * S + s] = sl[s][d];
    }
}

// ---------------- softmax row -> P split bf16 --------------------------------
__global__ __launch_bounds__(256) void softmax_kernel(
    const float* __restrict__ sc, bf16* __restrict__ ph,
    bf16* __restrict__ pl, int S)
{
    size_t row = blockIdx.x;
    const float* r = sc + row * (size_t)S;
    int tid = threadIdx.x;
    int nv = S >> 8;                      // 2 or 4
    float v[4];
    float m = -1e30f;
    for (int i = 0; i < nv; i++) { v[i] = r[tid + (i << 8)]; m = fmaxf(m, v[i]); }
    __shared__ float redM[8], redS[8];
    #pragma unroll
    for (int o = 16; o; o >>= 1) m = fmaxf(m, __shfl_xor_sync(~0u, m, o));
    if ((tid & 31) == 0) redM[tid >> 5] = m;
    __syncthreads();
    m = redM[0];
    #pragma unroll
    for (int i = 1; i < 8; i++) m = fmaxf(m, redM[i]);
    float sum = 0.f;
    for (int i = 0; i < nv; i++) { v[i] = __expf(v[i] - m); sum += v[i]; }
    #pragma unroll
    for (int o = 16; o; o >>= 1) sum += __shfl_xor_sync(~0u, sum, o);
    if ((tid & 31) == 0) redS[tid >> 5] = sum;
    __syncthreads();
    sum = redS[0];
    #pragma unroll
    for (int i = 1; i < 8; i++) sum += redS[i];
    float inv = 1.f / sum;
    for (int i = 0; i < nv; i++) {
        float p = v[i] * inv;
        bf16 h = __float2bfloat16(p);
        bf16 l = __float2bfloat16(p - __bfloat162float(h));
        ph[row * (size_t)S + tid + (i << 8)] = h;
        pl[row * (size_t)S + tid + (i << 8)] = l;
    }
}

// ---------------- orchestration ---------------------------------------------
extern "C" void kernel_launch(void* const* d_in, const int* in_sizes, int n_in,
                              void* d_out, int out_size)
{
    const float* x        = (const float*)d_in[0];
    const float* hid      = (const float*)d_in[1];
    const float* ln1_g    = (const float*)d_in[2];
    const float* ln1_b    = (const float*)d_in[3];
    const float* sa_in_w  = (const float*)d_in[4];
    const float* sa_in_b  = (const float*)d_in[5];
    const float* sa_out_w = (const float*)d_in[6];
    const float* sa_out_b = (const float*)d_in[7];
    const float* ln2_g    = (const float*)d_in[8];
    const float* ln2_b    = (const float*)d_in[9];
    const float* ca_in_w  = (const float*)d_in[10];
    const float* ca_in_b  = (const float*)d_in[11];
    const float* ca_out_w = (const float*)d_in[12];
    const float* ca_out_b = (const float*)d_in[13];
    const float* ln3_g    = (const float*)d_in[14];
    const float* ln3_b    = (const float*)d_in[15];
    const float* fc_w     = (const float*)d_in[16];
    const float* fc_b     = (const float*)d_in[17];
    const float* proj_w   = (const float*)d_in[18];
    const float* proj_b   = (const float*)d_in[19];
    float* out = (float*)d_out;

    bf16 *whi, *wlo, *hidh, *hidl, *hh, *hl, *qkvh, *qkvl, *kvh, *kvl;
    bf16 *vth, *vtl, *ph, *pl, *ctxh, *ctxl, *ffnh, *ffnl;
    float* scores;
    cudaGetSymbolAddress((void**)&whi,  g_w_hi);
    cudaGetSymbolAddress((void**)&wlo,  g_w_lo);
    cudaGetSymbolAddress((void**)&hidh, g_hid_hi);
    cudaGetSymbolAddress((void**)&hidl, g_hid_lo);
    cudaGetSymbolAddress((void**)&hh,   g_h_hi);
    cudaGetSymbolAddress((void**)&hl,   g_h_lo);
    cudaGetSymbolAddress((void**)&qkvh, g_qkv_hi);
    cudaGetSymbolAddress((void**)&qkvl, g_qkv_lo);
    cudaGetSymbolAddress((void**)&kvh,  g_kv_hi);
    cudaGetSymbolAddress((void**)&kvl,  g_kv_lo);
    cudaGetSymbolAddress((void**)&vth,  g_vt_hi);
    cudaGetSymbolAddress((void**)&vtl,  g_vt_lo);
    cudaGetSymbolAddress((void**)&scores, g_scores);
    cudaGetSymbolAddress((void**)&ph,   g_p_hi);
    cudaGetSymbolAddress((void**)&pl,   g_p_lo);
    cudaGetSymbolAddress((void**)&ctxh, g_ctx_hi);
    cudaGetSymbolAddress((void**)&ctxl, g_ctx_lo);
    cudaGetSymbolAddress((void**)&ffnh, g_ffn_hi);
    cudaGetSymbolAddress((void**)&ffnl, g_ffn_lo);

    const size_t TS_s = (size_t)T_LEN * 512;     // self scores per (b,h)
    const size_t TS_c = (size_t)T_LEN * 1024;    // cross scores per (b,h)

    // ---- one-time splits (weights + hidden_states) ----
    split_kernel<<<3072, 256>>>((const float4*)sa_in_w,
        (uint32_t*)(whi + WS_SA_IN), (uint32_t*)(wlo + WS_SA_IN));
    split_kernel<<<1024, 256>>>((const float4*)sa_out_w,
        (uint32_t*)(whi + WS_SA_OUT), (uint32_t*)(wlo + WS_SA_OUT));
    split_kernel<<<3072, 256>>>((const float4*)ca_in_w,
        (uint32_t*)(whi + WS_CA_IN), (uint32_t*)(wlo + WS_CA_IN));
    split_kernel<<<1024, 256>>>((const float4*)ca_out_w,
        (uint32_t*)(whi + WS_CA_OUT), (uint32_t*)(wlo + WS_CA_OUT));
    split_kernel<<<4096, 256>>>((const float4*)fc_w,
        (uint32_t*)(whi + WS_FC), (uint32_t*)(wlo + WS_FC));
    split_kernel<<<4096, 256>>>((const float4*)proj_w,
        (uint32_t*)(whi + WS_PROJ), (uint32_t*)(wlo + WS_PROJ));
    split_kernel<<<16384, 256>>>((const float4*)hid,
        (uint32_t*)hidh, (uint32_t*)hidl);

    // ================= self attention =================
    ln_split_kernel<<<MQ, 256>>>(x, ln1_g, ln1_b, hh, hl);
    gemm_bf16<128><<<dim3(24, 64, 1), 256>>>(
        hh, hl, 1024, 0, 0, whi + WS_SA_IN, wlo + WS_SA_IN, 1024, 0, 0,
        sa_in_b, nullptr, nullptr, qkvh, qkvl, 3072, 0, 0, 1024, 1.f, 0);
    vt_kernel<<<dim3(16, 1, 256), 256>>>(qkvh, qkvl, 3072, 2048, vth, vtl, 512);
    gemm_bf16<128><<<dim3(4, 4, 256), 256>>>(
        qkvh, qkvl, 49152, 3072, 64,
        qkvh + 1024, qkvl + 1024, 49152, 3072, 64,
        nullptr, nullptr, scores, nullptr, nullptr,
        512, 16 * TS_s, TS_s, 64, 0.125f, 0);
    softmax_kernel<<<256 * T_LEN, 256>>>(scores, ph, pl, 512);
    gemm_bf16<64><<<dim3(1, 4, 256), 256>>>(
        ph, pl, 512, 16 * TS_s, TS_s,
        vth, vtl, 512, (size_t)16 * 64 * 512, (size_t)64 * 512,
        nullptr, nullptr, nullptr, ctxh, ctxl,
        16384, 1024, 64, 512, 1.f, 0);
    gemm_bf16<128><<<dim3(8, 64, 1), 256>>>(
        ctxh, ctxl, 1024, 0, 0, whi + WS_SA_OUT, wlo + WS_SA_OUT, 1024, 0, 0,
        sa_out_b, x, out, nullptr, nullptr, 1024, 0, 0, 1024, 1.f, 0);

    // ================= cross attention =================
    ln_split_kernel<<<MQ, 256>>>(out, ln2_g, ln2_b, hh, hl);
    gemm_bf16<128><<<dim3(8, 64, 1), 256>>>(
        hh, hl, 1024, 0, 0, whi + WS_CA_IN, wlo + WS_CA_IN, 1024, 0, 0,
        ca_in_b, nullptr, nullptr, qkvh, qkvl, 1024, 0, 0, 1024, 1.f, 0);
    gemm_bf16<128><<<dim3(16, 128, 1), 256>>>(
        hidh, hidl, 1024, 0, 0,
        whi + WS_CA_IN + 1048576, wlo + WS_CA_IN + 1048576, 1024, 0, 0,
        ca_in_b + 1024, nullptr, nullptr, kvh, kvl, 2048, 0, 0, 1024, 1.f, 0);
    vt_kernel<<<dim3(32, 1, 256), 256>>>(kvh, kvl, 2048, 1024, vth, vtl, 1024);
    gemm_bf16<128><<<dim3(8, 4, 256), 256>>>(
        qkvh, qkvl, 16384, 1024, 64,
        kvh, kvl, 32768, 2048, 64,
        nullptr, nullptr, scores, nullptr, nullptr,
        1024, 16 * TS_c, TS_c, 64, 0.125f, 0);
    softmax_kernel<<<256 * T_LEN, 256>>>(scores, ph, pl, 1024);
    gemm_bf16<64><<<dim3(1, 4, 256), 256>>>(
        ph, pl, 1024, 16 * TS_c, TS_c,
        vth, vtl, 1024, (size_t)16 * 64 * 1024, (size_t)64 * 1024,
        nullptr, nullptr, nullptr, ctxh, ctxl,
        16384, 1024, 64, 1024, 1.f, 0);
    gemm_bf16<128><<<dim3(8, 64, 1), 256>>>(
        ctxh, ctxl, 1024, 0, 0, whi + WS_CA_OUT, wlo + WS_CA_OUT, 1024, 0, 0,
        ca_out_b, out, out, nullptr, nullptr, 1024, 0, 0, 1024, 1.f, 0);

    // ================= MLP =================
    ln_split_kernel<<<MQ, 256>>>(out, ln3_g, ln3_b, hh, hl);
    gemm_bf16<128><<<dim3(32, 64, 1), 256>>>(
        hh, hl, 1024, 0, 0, whi + WS_FC, wlo + WS_FC, 1024, 0, 0,
        fc_b, nullptr, nullptr, ffnh, ffnl, 4096, 0, 0, 1024, 1.f, 1);
    gemm_bf16<128><<<dim3(8, 64, 1), 256>>>(
        ffnh, ffnl, 4096, 0, 0, whi + WS_PROJ, wlo + WS_PROJ, 4096, 0, 0,
        proj_b, out, out, nullptr, nullptr, 1024, 0, 0, 4096, 1.f, 0);
}

// round 5
// speedup vs baseline: 3.8356x; 1.5504x over previous
#include <cuda_runtime.h>
#include <cuda_bf16.h>
#include <math.h>
#include <stdint.h>

#define D_MODEL 1024
#define N_HEAD  16
#define T_LEN   512
#define S_LEN   1024
#define BATCH   16
#define MQ      (T_LEN * BATCH)   /* 8192  query rows  */
#define MKV     (S_LEN * BATCH)   /* 16384 kv rows     */
typedef __nv_bfloat16 bf16;

// ---------------- scratch (static device globals; no allocation) ------------
#define WS_SA_IN  0u
#define WS_SA_OUT (3u*1024*1024)
#define WS_CA_IN  (4u*1024*1024)
#define WS_CA_OUT (7u*1024*1024)
#define WS_FC     (8u*1024*1024)
#define WS_PROJ   (12u*1024*1024)
#define WS_TOTAL  (16u*1024*1024)
__device__ bf16  g_w_hi[WS_TOTAL],        g_w_lo[WS_TOTAL];
__device__ bf16  g_hid_hi[MKV*D_MODEL],   g_hid_lo[MKV*D_MODEL];
__device__ bf16  g_h_hi[MQ*D_MODEL],      g_h_lo[MQ*D_MODEL];
__device__ bf16  g_qkv_hi[MQ*3*D_MODEL],  g_qkv_lo[MQ*3*D_MODEL];
__device__ bf16  g_kv_hi[MKV*2*D_MODEL],  g_kv_lo[MKV*2*D_MODEL];
__device__ bf16  g_vt_hi[256*64*S_LEN],   g_vt_lo[256*64*S_LEN];
__device__ float g_scores[134217728];                       // 256*512*1024
__device__ bf16  g_p_hi[134217728],       g_p_lo[134217728];
__device__ bf16  g_ctx_hi[MQ*D_MODEL],    g_ctx_lo[MQ*D_MODEL];
__device__ bf16  g_ffn_hi[MQ*4*D_MODEL],  g_ffn_lo[MQ*4*D_MODEL];

__device__ __forceinline__ uint32_t b2u(__nv_bfloat162 x) {
    return *reinterpret_cast<uint32_t*>(&x);
}
__device__ __forceinline__ uint32_t smem_u32(const void* p) {
    uint32_t a;
    asm("{ .reg .u64 t; cvta.to.shared.u64 t, %1; cvt.u32.u64 %0, t; }"
        : "=r"(a) : "l"(p));
    return a;
}
__device__ __forceinline__ void cp_async16(uint32_t s, const void* g) {
    asm volatile("cp.async.cg.shared.global [%0], [%1], 16;" :: "r"(s), "l"(g));
}
__device__ __forceinline__ void cp_commit() {
    asm volatile("cp.async.commit_group;");
}
__device__ __forceinline__ void cp_wait1() {
    asm volatile("cp.async.wait_group 1;");
}
__device__ __forceinline__ void ldsm4(uint32_t* r, uint32_t addr) {
    asm volatile("ldmatrix.sync.aligned.m8n8.x4.shared.b16 {%0,%1,%2,%3}, [%4];"
                 : "=r"(r[0]), "=r"(r[1]), "=r"(r[2]), "=r"(r[3]) : "r"(addr));
}
// mma.sync m16n8k16 bf16 (sm_80+)
__device__ __forceinline__ void mma_bf16(float* c, const uint32_t* a,
                                         const uint32_t* b) {
    asm volatile(
        "mma.sync.aligned.m16n8k16.row.col.f32.bf16.bf16.f32 "
        "{%0,%1,%2,%3}, {%4,%5,%6,%7}, {%8,%9}, {%0,%1,%2,%3};"
        : "+f"(c[0]), "+f"(c[1]), "+f"(c[2]), "+f"(c[3])
        : "r"(a[0]), "r"(a[1]), "r"(a[2]), "r"(a[3]),
          "r"(b[0]), "r"(b[1]));
}

// ======================= tensor-core GEMM ===================================
// C[m,n] = sum_k A[m,k]*B[n,k], bf16 hi/lo pairs (3-pass split), fp32 accum.
// Tile 128 x TN, BK=32. 2-stage cp.async pipeline, XOR-swizzled k-major smem,
// ldmatrix fragment loads. 8 warps 4x2. Batched via z = b*16 + h.
template<int TN>
__global__ __launch_bounds__(256, 2) void gemm_bf16(
    const bf16* __restrict__ Ah, const bf16* __restrict__ Al,
    int lda, size_t sAb, size_t sAh,
    const bf16* __restrict__ Bh, const bf16* __restrict__ Bl,
    int ldb, size_t sBb, size_t sBh,
    const float* __restrict__ bias,
    const float* __restrict__ res,
    float* __restrict__ Cf, bf16* __restrict__ Chi, bf16* __restrict__ Clo,
    int ldc, size_t sCb, size_t sCh,
    int K, float oscale, int act)
{
    constexpr int NT    = TN / 16;        // n-subtiles per warp
    constexpr int TNB   = TN * 64;        // bytes per B plane
    constexpr int STAGE = 16384 + 2 * TNB;
    extern __shared__ char dsm[];
    const uint32_t smem_base = smem_u32(dsm);

    const int tid = threadIdx.x, wid = tid >> 5, lane = tid & 31;
    const int wm = wid >> 1, wn = wid & 1;
    const int m0 = blockIdx.y * 128, n0 = blockIdx.x * TN;
    const int zb = blockIdx.z >> 4, zh = blockIdx.z & 15;

    const bf16* pAh = Ah + (size_t)zb * sAb + (size_t)zh * sAh;
    const bf16* pAl = Al + (size_t)zb * sAb + (size_t)zh * sAh;
    const bf16* pBh = Bh + (size_t)zb * sBb + (size_t)zh * sBh;
    const bf16* pBl = Bl + (size_t)zb * sBb + (size_t)zh * sBh;

    float acc[2][NT][4];
    #pragma unroll
    for (int i = 0; i < 2; i++)
        #pragma unroll
        for (int j = 0; j < NT; j++)
            #pragma unroll
            for (int q = 0; q < 4; q++) acc[i][j][q] = 0.f;

    const int nCh = K >> 5;

    auto issue = [&](int c, int s) {
        const int k0 = c << 5;
        const uint32_t sb = smem_base + s * STAGE;
        #pragma unroll
        for (int it = 0; it < 2; it++) {
            int j = tid + (it << 8);
            int r = j >> 2, q = j & 3;
            uint32_t so = sb + r * 64 + ((q ^ ((r >> 1) & 3)) << 4);
            size_t g = (size_t)(m0 + r) * lda + k0 + q * 8;
            cp_async16(so,        pAh + g);
            cp_async16(so + 8192, pAl + g);
        }
        #pragma unroll
        for (int it = 0; it < TN / 64; it++) {
            int j = tid + (it << 8);
            int n = j >> 2, q = j & 3;
            uint32_t so = sb + 16384 + n * 64 + ((q ^ ((n >> 1) & 3)) << 4);
            size_t g = (size_t)(n0 + n) * ldb + k0 + q * 8;
            cp_async16(so,       pBh + g);
            cp_async16(so + TNB, pBl + g);
        }
    };

    issue(0, 0); cp_commit();
    issue(1, 1); cp_commit();

    for (int c = 0; c < nCh; c++) {
        const int s = c & 1;
        cp_wait1();
        __syncthreads();
        const uint32_t sb = smem_base + s * STAGE;
        #pragma unroll
        for (int ks = 0; ks < 2; ks++) {
            uint32_t aH[2][4], aL[2][4];
            #pragma unroll
            for (int mt = 0; mt < 2; mt++) {
                int row = wm * 32 + mt * 16 + (lane & 15);
                int cc  = 2 * ks + (lane >> 4);
                uint32_t off = row * 64 + ((cc ^ ((row >> 1) & 3)) << 4);
                ldsm4(aH[mt], sb + off);
                ldsm4(aL[mt], sb + 8192 + off);
            }
            #pragma unroll
            for (int ntp = 0; ntp < NT / 2; ntp++) {
                int nrow = wn * (TN / 2) + ntp * 16 + (lane & 7)
                         + ((lane & 16) ? 8 : 0);
                int cc   = 2 * ks + ((lane >> 3) & 1);
                uint32_t off = nrow * 64 + ((cc ^ ((nrow >> 1) & 3)) << 4);
                uint32_t bH[4], bL[4];
                ldsm4(bH, sb + 16384 + off);
                ldsm4(bL, sb + 16384 + TNB + off);
                #pragma unroll
                for (int half = 0; half < 2; half++) {
                    int nt = ntp * 2 + half;
                    mma_bf16(acc[0][nt], aH[0], bH + half * 2);
                    mma_bf16(acc[1][nt], aH[1], bH + half * 2);
                    mma_bf16(acc[0][nt], aH[0], bL + half * 2);
                    mma_bf16(acc[1][nt], aH[1], bL + half * 2);
                    mma_bf16(acc[0][nt], aL[0], bH + half * 2);
                    mma_bf16(acc[1][nt], aL[1], bH + half * 2);
                }
            }
        }
        __syncthreads();
        if (c + 2 < nCh) issue(c + 2, s);
        cp_commit();
    }

    // ---- epilogue ----
    const int r0 = m0 + wm * 32 + (lane >> 2);
    const int c0 = n0 + wn * (TN / 2) + (lane & 3) * 2;
    const size_t zoff = (size_t)zb * sCb + (size_t)zh * sCh;
    #pragma unroll
    for (int mt = 0; mt < 2; mt++) {
        #pragma unroll
        for (int nt = 0; nt < NT; nt++) {
            int col = c0 + nt * 8;
            float2 bv = make_float2(0.f, 0.f);
            if (bias) bv = *(const float2*)(bias + col);
            #pragma unroll
            for (int hrow = 0; hrow < 2; hrow++) {
                int row = r0 + mt * 16 + hrow * 8;
                float2 vv;
                vv.x = acc[mt][nt][hrow * 2 + 0] * oscale + bv.x;
                vv.y = acc[mt][nt][hrow * 2 + 1] * oscale + bv.y;
                size_t co = (size_t)row * ldc + col + zoff;
                if (res) {
                    float2 rr = *(const float2*)(res + co);
                    vv.x += rr.x; vv.y += rr.y;
                }
                if (act) {
                    vv.x = vv.x / (1.f + __expf(-1.702f * vv.x));
                    vv.y = vv.y / (1.f + __expf(-1.702f * vv.y));
                }
                if (Cf) {
                    *(float2*)(Cf + co) = vv;
                } else {
                    bf16 hx = __float2bfloat16(vv.x);
                    bf16 hy = __float2bfloat16(vv.y);
                    *(uint32_t*)(Chi + co) = b2u(__halves2bfloat162(hx, hy));
                    bf16 lx = __float2bfloat16(vv.x - __bfloat162float(hx));
                    bf16 ly = __float2bfloat16(vv.y - __bfloat162float(hy));
                    *(uint32_t*)(Clo + co) = b2u(__halves2bfloat162(lx, ly));
                }
            }
        }
    }
}

// ---------------- split fp32 -> bf16 hi/lo -----------------------------------
__global__ __launch_bounds__(256) void split_kernel(
    const float4* __restrict__ src, uint32_t* __restrict__ hi,
    uint32_t* __restrict__ lo)
{
    size_t i = (size_t)blockIdx.x * 256 + threadIdx.x;
    float4 v = src[i];
    __nv_bfloat162 h01 = __floats2bfloat162_rn(v.x, v.y);
    __nv_bfloat162 h23 = __floats2bfloat162_rn(v.z, v.w);
    float2 f01 = __bfloat1622float2(h01);
    float2 f23 = __bfloat1622float2(h23);
    __nv_bfloat162 l01 = __floats2bfloat162_rn(v.x - f01.x, v.y - f01.y);
    __nv_bfloat162 l23 = __floats2bfloat162_rn(v.z - f23.x, v.w - f23.y);
    hi[i * 2]     = b2u(h01);
    hi[i * 2 + 1] = b2u(h23);
    lo[i * 2]     = b2u(l01);
    lo[i * 2 + 1] = b2u(l23);
}

// ---------------- LayerNorm -> split bf16 ------------------------------------
__global__ __launch_bounds__(256) void ln_split_kernel(
    const float* __restrict__ x, const float* __restrict__ g,
    const float* __restrict__ b, bf16* __restrict__ yh, bf16* __restrict__ yl)
{
    int row = blockIdx.x;
    const float4* xr = (const float4*)(x + (size_t)row * D_MODEL);
    int tid = threadIdx.x;
    float4 v = xr[tid];
    float s  = v.x + v.y + v.z + v.w;
    float ss = v.x*v.x + v.y*v.y + v.z*v.z + v.w*v.w;
    #pragma unroll
    for (int o = 16; o; o >>= 1) {
        s  += __shfl_xor_sync(~0u, s,  o);
        ss += __shfl_xor_sync(~0u, ss, o);
    }
    __shared__ float smS[8], smSS[8];
    int w = tid >> 5;
    if ((tid & 31) == 0) { smS[w] = s; smSS[w] = ss; }
    __syncthreads();
    if (tid < 32) {
        s  = (tid < 8) ? smS[tid]  : 0.f;
        ss = (tid < 8) ? smSS[tid] : 0.f;
        #pragma unroll
        for (int o = 4; o; o >>= 1) {
            s  += __shfl_xor_sync(~0u, s,  o);
            ss += __shfl_xor_sync(~0u, ss, o);
        }
        if (tid == 0) { smS[0] = s; smSS[0] = ss; }
    }
    __syncthreads();
    float mean = smS[0] * (1.f / D_MODEL);
    float var  = smSS[0] * (1.f / D_MODEL) - mean * mean;
    float rstd = rsqrtf(var + 1e-5f);
    float4 gv = ((const float4*)g)[tid];
    float4 bv = ((const float4*)b)[tid];
    float4 o;
    o.x = (v.x - mean) * rstd * gv.x + bv.x;
    o.y = (v.y - mean) * rstd * gv.y + bv.y;
    o.z = (v.z - mean) * rstd * gv.z + bv.z;
    o.w = (v.w - mean) * rstd * gv.w + bv.w;
    __nv_bfloat162 h01 = __floats2bfloat162_rn(o.x, o.y);
    __nv_bfloat162 h23 = __floats2bfloat162_rn(o.z, o.w);
    float2 f01 = __bfloat1622float2(h01);
    float2 f23 = __bfloat1622float2(h23);
    __nv_bfloat162 l01 = __floats2bfloat162_rn(o.x - f01.x, o.y - f01.y);
    __nv_bfloat162 l23 = __floats2bfloat162_rn(o.z - f23.x, o.w - f23.y);
    uint32_t* yhr = (uint32_t*)(yh + (size_t)row * D_MODEL);
    uint32_t* ylr = (uint32_t*)(yl + (size_t)row * D_MODEL);
    yhr[tid * 2]     = b2u(h01);
    yhr[tid * 2 + 1] = b2u(h23);
    ylr[tid * 2]     = b2u(l01);
    ylr[tid * 2 + 1] = b2u(l23);
}

// ---------------- V transpose: vt[z][d][s] from kv-style layout --------------
__global__ __launch_bounds__(256) void vt_kernel(
    const bf16* __restrict__ inh, const bf16* __restrict__ inl,
    int ldin, int off,
    bf16* __restrict__ outh, bf16* __restrict__ outl, int S)
{
    int z = blockIdx.z, b = z >> 4, hh = z & 15;
    int s0 = blockIdx.x * 32;
    __shared__ uint16_t sh[32][66], sl[32][66];
    int tid = threadIdx.x;
    int d2 = (tid & 31) * 2, srow = tid >> 5;
    #pragma unroll
    for (int p = 0; p < 4; p++) {
        int s = srow + p * 8;
        size_t g = (size_t)((s0 + s) * BATCH + b) * ldin + off + hh * 64 + d2;
        uint32_t vh = *(const uint32_t*)(inh + g);
        uint32_t vl = *(const uint32_t*)(inl + g);
        sh[s][d2] = (uint16_t)(vh & 0xffff); sh[s][d2 + 1] = (uint16_t)(vh >> 16);
        sl[s][d2] = (uint16_t)(vl & 0xffff); sl[s][d2 + 1] = (uint16_t)(vl >> 16);
    }
    __syncthreads();
    size_t obase = (size_t)z * 64 * S + s0;
    uint16_t* oh = (uint16_t*)outh;
    uint16_t* ol = (uint16_t*)outl;
    #pragma unroll
    for (int p = 0; p < 8; p++) {
        int d = (tid >> 5) + p * 8;
        int s = tid & 31;
        oh[obase + (size_t)d * S + s] = sh[s][d];
        ol[obase + (size_t)d * S + s] = sl[s][d];
    }
}

// ---------------- softmax row -> P split bf16 --------------------------------
__global__ __launch_bounds__(256) void softmax_kernel(
    const float* __restrict__ sc, bf16* __restrict__ ph,
    bf16* __restrict__ pl, int S)
{
    size_t row = blockIdx.x;
    const float* r = sc + row * (size_t)S;
    int tid = threadIdx.x;
    int nv = S >> 8;                      // 2 or 4
    float v[4];
    float m = -1e30f;
    for (int i = 0; i < nv; i++) { v[i] = r[tid + (i << 8)]; m = fmaxf(m, v[i]); }
    __shared__ float redM[8], redS[8];
    #pragma unroll
    for (int o = 16; o; o >>= 1) m = fmaxf(m, __shfl_xor_sync(~0u, m, o));
    if ((tid & 31) == 0) redM[tid >> 5] = m;
    __syncthreads();
    m = redM[0];
    #pragma unroll
    for (int i = 1; i < 8; i++) m = fmaxf(m, redM[i]);
    float sum = 0.f;
    for (int i = 0; i < nv; i++) { v[i] = __expf(v[i] - m); sum += v[i]; }
    #pragma unroll
    for (int o = 16; o; o >>= 1) sum += __shfl_xor_sync(~0u, sum, o);
    if ((tid & 31) == 0) redS[tid >> 5] = sum;
    __syncthreads();
    sum = redS[0];
    #pragma unroll
    for (int i = 1; i < 8; i++) sum += redS[i];
    float inv = 1.f / sum;
    for (int i = 0; i < nv; i++) {
        float p = v[i] * inv;
        bf16 h = __float2bfloat16(p);
        bf16 l = __float2bfloat16(p - __bfloat162float(h));
        ph[row * (size_t)S + tid + (i << 8)] = h;
        pl[row * (size_t)S + tid + (i << 8)] = l;
    }
}

// ---------------- orchestration ---------------------------------------------
extern "C" void kernel_launch(void* const* d_in, const int* in_sizes, int n_in,
                              void* d_out, int out_size)
{
    const float* x        = (const float*)d_in[0];
    const float* hid      = (const float*)d_in[1];
    const float* ln1_g    = (const float*)d_in[2];
    const float* ln1_b    = (const float*)d_in[3];
    const float* sa_in_w  = (const float*)d_in[4];
    const float* sa_in_b  = (const float*)d_in[5];
    const float* sa_out_w = (const float*)d_in[6];
    const float* sa_out_b = (const float*)d_in[7];
    const float* ln2_g    = (const float*)d_in[8];
    const float* ln2_b    = (const float*)d_in[9];
    const float* ca_in_w  = (const float*)d_in[10];
    const float* ca_in_b  = (const float*)d_in[11];
    const float* ca_out_w = (const float*)d_in[12];
    const float* ca_out_b = (const float*)d_in[13];
    const float* ln3_g    = (const float*)d_in[14];
    const float* ln3_b    = (const float*)d_in[15];
    const float* fc_w     = (const float*)d_in[16];
    const float* fc_b     = (const float*)d_in[17];
    const float* proj_w   = (const float*)d_in[18];
    const float* proj_b   = (const float*)d_in[19];
    float* out = (float*)d_out;

    bf16 *whi, *wlo, *hidh, *hidl, *hh, *hl, *qkvh, *qkvl, *kvh, *kvl;
    bf16 *vth, *vtl, *ph, *pl, *ctxh, *ctxl, *ffnh, *ffnl;
    float* scores;
    cudaGetSymbolAddress((void**)&whi,  g_w_hi);
    cudaGetSymbolAddress((void**)&wlo,  g_w_lo);
    cudaGetSymbolAddress((void**)&hidh, g_hid_hi);
    cudaGetSymbolAddress((void**)&hidl, g_hid_lo);
    cudaGetSymbolAddress((void**)&hh,   g_h_hi);
    cudaGetSymbolAddress((void**)&hl,   g_h_lo);
    cudaGetSymbolAddress((void**)&qkvh, g_qkv_hi);
    cudaGetSymbolAddress((void**)&qkvl, g_qkv_lo);
    cudaGetSymbolAddress((void**)&kvh,  g_kv_hi);
    cudaGetSymbolAddress((void**)&kvl,  g_kv_lo);
    cudaGetSymbolAddress((void**)&vth,  g_vt_hi);
    cudaGetSymbolAddress((void**)&vtl,  g_vt_lo);
    cudaGetSymbolAddress((void**)&scores, g_scores);
    cudaGetSymbolAddress((void**)&ph,   g_p_hi);
    cudaGetSymbolAddress((void**)&pl,   g_p_lo);
    cudaGetSymbolAddress((void**)&ctxh, g_ctx_hi);
    cudaGetSymbolAddress((void**)&ctxl, g_ctx_lo);
    cudaGetSymbolAddress((void**)&ffnh, g_ffn_hi);
    cudaGetSymbolAddress((void**)&ffnl, g_ffn_lo);

    const int SM128 = 65536, SM64 = 49152;
    cudaFuncSetAttribute(gemm_bf16<128>,
                         cudaFuncAttributeMaxDynamicSharedMemorySize, SM128);
    cudaFuncSetAttribute(gemm_bf16<64>,
                         cudaFuncAttributeMaxDynamicSharedMemorySize, SM64);

    const size_t TS_s = (size_t)T_LEN * 512;     // self scores per (b,h)
    const size_t TS_c = (size_t)T_LEN * 1024;    // cross scores per (b,h)

    // ---- one-time splits (weights + hidden_states) ----
    split_kernel<<<3072, 256>>>((const float4*)sa_in_w,
        (uint32_t*)(whi + WS_SA_IN), (uint32_t*)(wlo + WS_SA_IN));
    split_kernel<<<1024, 256>>>((const float4*)sa_out_w,
        (uint32_t*)(whi + WS_SA_OUT), (uint32_t*)(wlo + WS_SA_OUT));
    split_kernel<<<3072, 256>>>((const float4*)ca_in_w,
        (uint32_t*)(whi + WS_CA_IN), (uint32_t*)(wlo + WS_CA_IN));
    split_kernel<<<1024, 256>>>((const float4*)ca_out_w,
        (uint32_t*)(whi + WS_CA_OUT), (uint32_t*)(wlo + WS_CA_OUT));
    split_kernel<<<4096, 256>>>((const float4*)fc_w,
        (uint32_t*)(whi + WS_FC), (uint32_t*)(wlo + WS_FC));
    split_kernel<<<4096, 256>>>((const float4*)proj_w,
        (uint32_t*)(whi + WS_PROJ), (uint32_t*)(wlo + WS_PROJ));
    split_kernel<<<16384, 256>>>((const float4*)hid,
        (uint32_t*)hidh, (uint32_t*)hidl);

    // ================= self attention =================
    ln_split_kernel<<<MQ, 256>>>(x, ln1_g, ln1_b, hh, hl);
    gemm_bf16<128><<<dim3(24, 64, 1), 256, SM128>>>(
        hh, hl, 1024, 0, 0, whi + WS_SA_IN, wlo + WS_SA_IN, 1024, 0, 0,
        sa_in_b, nullptr, nullptr, qkvh, qkvl, 3072, 0, 0, 1024, 1.f, 0);
    vt_kernel<<<dim3(16, 1, 256), 256>>>(qkvh, qkvl, 3072, 2048, vth, vtl, 512);
    gemm_bf16<128><<<dim3(4, 4, 256), 256, SM128>>>(
        qkvh, qkvl, 49152, 3072, 64,
        qkvh + 1024, qkvl + 1024, 49152, 3072, 64,
        nullptr, nullptr, scores, nullptr, nullptr,
        512, 16 * TS_s, TS_s, 64, 0.125f, 0);
    softmax_kernel<<<256 * T_LEN, 256>>>(scores, ph, pl, 512);
    gemm_bf16<64><<<dim3(1, 4, 256), 256, SM64>>>(
        ph, pl, 512, 16 * TS_s, TS_s,
        vth, vtl, 512, (size_t)16 * 64 * 512, (size_t)64 * 512,
        nullptr, nullptr, nullptr, ctxh, ctxl,
        16384, 1024, 64, 512, 1.f, 0);
    gemm_bf16<128><<<dim3(8, 64, 1), 256, SM128>>>(
        ctxh, ctxl, 1024, 0, 0, whi + WS_SA_OUT, wlo + WS_SA_OUT, 1024, 0, 0,
        sa_out_b, x, out, nullptr, nullptr, 1024, 0, 0, 1024, 1.f, 0);

    // ================= cross attention =================
    ln_split_kernel<<<MQ, 256>>>(out, ln2_g, ln2_b, hh, hl);
    gemm_bf16<128><<<dim3(8, 64, 1), 256, SM128>>>(
        hh, hl, 1024, 0, 0, whi + WS_CA_IN, wlo + WS_CA_IN, 1024, 0, 0,
        ca_in_b, nullptr, nullptr, qkvh, qkvl, 1024, 0, 0, 1024, 1.f, 0);
    gemm_bf16<128><<<dim3(16, 128, 1), 256, SM128>>>(
        hidh, hidl, 1024, 0, 0,
        whi + WS_CA_IN + 1048576, wlo + WS_CA_IN + 1048576, 1024, 0, 0,
        ca_in_b + 1024, nullptr, nullptr, kvh, kvl, 2048, 0, 0, 1024, 1.f, 0);
    vt_kernel<<<dim3(32, 1, 256), 256>>>(kvh, kvl, 2048, 1024, vth, vtl, 1024);
    gemm_bf16<128><<<dim3(8, 4, 256), 256, SM128>>>(
        qkvh, qkvl, 16384, 1024, 64,
        kvh, kvl, 32768, 2048, 64,
        nullptr, nullptr, scores, nullptr, nullptr,
        1024, 16 * TS_c, TS_c, 64, 0.125f, 0);
    softmax_kernel<<<256 * T_LEN, 256>>>(scores, ph, pl, 1024);
    gemm_bf16<64><<<dim3(1, 4, 256), 256, SM64>>>(
        ph, pl, 1024, 16 * TS_c, TS_c,
        vth, vtl, 1024, (size_t)16 * 64 * 1024, (size_t)64 * 1024,
        nullptr, nullptr, nullptr, ctxh, ctxl,
        16384, 1024, 64, 1024, 1.f, 0);
    gemm_bf16<128><<<dim3(8, 64, 1), 256, SM128>>>(
        ctxh, ctxl, 1024, 0, 0, whi + WS_CA_OUT, wlo + WS_CA_OUT, 1024, 0, 0,
        ca_out_b, out, out, nullptr, nullptr, 1024, 0, 0, 1024, 1.f, 0);

    // ================= MLP =================
    ln_split_kernel<<<MQ, 256>>>(out, ln3_g, ln3_b, hh, hl);
    gemm_bf16<128><<<dim3(32, 64, 1), 256, SM128>>>(
        hh, hl, 1024, 0, 0, whi + WS_FC, wlo + WS_FC, 1024, 0, 0,
        fc_b, nullptr, nullptr, ffnh, ffnl, 4096, 0, 0, 1024, 1.f, 1);
    gemm_bf16<128><<<dim3(8, 64, 1), 256, SM128>>>(
        ffnh, ffnl, 4096, 0, 0, whi + WS_PROJ, wlo + WS_PROJ, 4096, 0, 0,
        proj_b, out, out, nullptr, nullptr, 1024, 0, 0, 4096, 1.f, 0);
}

// round 6
// speedup vs baseline: 4.8319x; 1.2597x over previous
#include <cuda_runtime.h>
#include <cuda_bf16.h>
#include <math.h>
#include <stdint.h>

#define D_MODEL 1024
#define N_HEAD  16
#define T_LEN   512
#define S_LEN   1024
#define BATCH   16
#define MQ      (T_LEN * BATCH)   /* 8192  query rows  */
#define MKV     (S_LEN * BATCH)   /* 16384 kv rows     */
typedef __nv_bfloat16 bf16;

// ---------------- scratch (static device globals; no allocation) ------------
#define WS_SA_IN  0u
#define WS_SA_OUT (3u*1024*1024)
#define WS_CA_IN  (4u*1024*1024)
#define WS_CA_OUT (7u*1024*1024)
#define WS_FC     (8u*1024*1024)
#define WS_PROJ   (12u*1024*1024)
#define WS_TOTAL  (16u*1024*1024)
__device__ bf16  g_w_hi[WS_TOTAL],        g_w_lo[WS_TOTAL];
__device__ bf16  g_hid_hi[MKV*D_MODEL],   g_hid_lo[MKV*D_MODEL];
__device__ bf16  g_h_hi[MQ*D_MODEL],      g_h_lo[MQ*D_MODEL];
__device__ bf16  g_qkv_hi[MQ*3*D_MODEL],  g_qkv_lo[MQ*3*D_MODEL];
__device__ bf16  g_kv_hi[MKV*2*D_MODEL],  g_kv_lo[MKV*2*D_MODEL];
__device__ bf16  g_ctx_hi[MQ*D_MODEL],    g_ctx_lo[MQ*D_MODEL];
__device__ bf16  g_ffn_hi[MQ*4*D_MODEL],  g_ffn_lo[MQ*4*D_MODEL];

__device__ __forceinline__ uint32_t b2u(__nv_bfloat162 x) {
    return *reinterpret_cast<uint32_t*>(&x);
}
__device__ __forceinline__ uint32_t smem_u32(const void* p) {
    uint32_t a;
    asm("{ .reg .u64 t; cvta.to.shared.u64 t, %1; cvt.u32.u64 %0, t; }"
        : "=r"(a) : "l"(p));
    return a;
}
__device__ __forceinline__ void cp_async16(uint32_t s, const void* g) {
    asm volatile("cp.async.cg.shared.global [%0], [%1], 16;" :: "r"(s), "l"(g));
}
__device__ __forceinline__ void cp_commit() {
    asm volatile("cp.async.commit_group;");
}
__device__ __forceinline__ void cp_wait1() {
    asm volatile("cp.async.wait_group 1;");
}
__device__ __forceinline__ void ldsm4(uint32_t* r, uint32_t addr) {
    asm volatile("ldmatrix.sync.aligned.m8n8.x4.shared.b16 {%0,%1,%2,%3}, [%4];"
                 : "=r"(r[0]), "=r"(r[1]), "=r"(r[2]), "=r"(r[3]) : "r"(addr));
}
__device__ __forceinline__ void ldsm4t(uint32_t* r, uint32_t addr) {
    asm volatile("ldmatrix.sync.aligned.m8n8.x4.trans.shared.b16 {%0,%1,%2,%3}, [%4];"
                 : "=r"(r[0]), "=r"(r[1]), "=r"(r[2]), "=r"(r[3]) : "r"(addr));
}
__device__ __forceinline__ void mma_bf16(float* c, const uint32_t* a,
                                         const uint32_t* b) {
    asm volatile(
        "mma.sync.aligned.m16n8k16.row.col.f32.bf16.bf16.f32 "
        "{%0,%1,%2,%3}, {%4,%5,%6,%7}, {%8,%9}, {%0,%1,%2,%3};"
        : "+f"(c[0]), "+f"(c[1]), "+f"(c[2]), "+f"(c[3])
        : "r"(a[0]), "r"(a[1]), "r"(a[2]), "r"(a[3]),
          "r"(b[0]), "r"(b[1]));
}
__device__ __forceinline__ void pack2(float x, float y,
                                      uint32_t& hi, uint32_t& lo) {
    __nv_bfloat162 h = __floats2bfloat162_rn(x, y);
    float2 f = __bfloat1622float2(h);
    __nv_bfloat162 l = __floats2bfloat162_rn(x - f.x, y - f.y);
    hi = b2u(h); lo = b2u(l);
}

// ======================= tensor-core GEMM (linear layers) ====================
template<int TN>
__global__ __launch_bounds__(256, 2) void gemm_bf16(
    const bf16* __restrict__ Ah, const bf16* __restrict__ Al, int lda,
    const bf16* __restrict__ Bh, const bf16* __restrict__ Bl, int ldb,
    const float* __restrict__ bias,
    const float* __restrict__ res,
    float* __restrict__ Cf, bf16* __restrict__ Chi, bf16* __restrict__ Clo,
    int ldc, int K, int act)
{
    constexpr int NT    = TN / 16;
    constexpr int TNB   = TN * 64;
    constexpr int STAGE = 16384 + 2 * TNB;
    extern __shared__ char dsm[];
    const uint32_t smem_base = smem_u32(dsm);

    const int tid = threadIdx.x, wid = tid >> 5, lane = tid & 31;
    const int wm = wid >> 1, wn = wid & 1;
    const int m0 = blockIdx.y * 128, n0 = blockIdx.x * TN;

    float acc[2][NT][4];
    #pragma unroll
    for (int i = 0; i < 2; i++)
        #pragma unroll
        for (int j = 0; j < NT; j++)
            #pragma unroll
            for (int q = 0; q < 4; q++) acc[i][j][q] = 0.f;

    const int nCh = K >> 5;
    auto issue = [&](int c, int s) {
        const int k0 = c << 5;
        const uint32_t sb = smem_base + s * STAGE;
        #pragma unroll
        for (int it = 0; it < 2; it++) {
            int j = tid + (it << 8);
            int r = j >> 2, q = j & 3;
            uint32_t so = sb + r * 64 + ((q ^ ((r >> 1) & 3)) << 4);
            size_t g = (size_t)(m0 + r) * lda + k0 + q * 8;
            cp_async16(so,        Ah + g);
            cp_async16(so + 8192, Al + g);
        }
        #pragma unroll
        for (int it = 0; it < TN / 64; it++) {
            int j = tid + (it << 8);
            int n = j >> 2, q = j & 3;
            uint32_t so = sb + 16384 + n * 64 + ((q ^ ((n >> 1) & 3)) << 4);
            size_t g = (size_t)(n0 + n) * ldb + k0 + q * 8;
            cp_async16(so,       Bh + g);
            cp_async16(so + TNB, Bl + g);
        }
    };

    issue(0, 0); cp_commit();
    issue(1, 1); cp_commit();

    for (int c = 0; c < nCh; c++) {
        const int s = c & 1;
        cp_wait1();
        __syncthreads();
        const uint32_t sb = smem_base + s * STAGE;
        #pragma unroll
        for (int ks = 0; ks < 2; ks++) {
            uint32_t aH[2][4], aL[2][4];
            #pragma unroll
            for (int mt = 0; mt < 2; mt++) {
                int row = wm * 32 + mt * 16 + (lane & 15);
                int cc  = 2 * ks + (lane >> 4);
                uint32_t off = row * 64 + ((cc ^ ((row >> 1) & 3)) << 4);
                ldsm4(aH[mt], sb + off);
                ldsm4(aL[mt], sb + 8192 + off);
            }
            #pragma unroll
            for (int ntp = 0; ntp < NT / 2; ntp++) {
                int nrow = wn * (TN / 2) + ntp * 16 + (lane & 7)
                         + ((lane & 16) ? 8 : 0);
                int cc   = 2 * ks + ((lane >> 3) & 1);
                uint32_t off = nrow * 64 + ((cc ^ ((nrow >> 1) & 3)) << 4);
                uint32_t bH[4], bL[4];
                ldsm4(bH, sb + 16384 + off);
                ldsm4(bL, sb + 16384 + TNB + off);
                #pragma unroll
                for (int half = 0; half < 2; half++) {
                    int nt = ntp * 2 + half;
                    mma_bf16(acc[0][nt], aH[0], bH + half * 2);
                    mma_bf16(acc[1][nt], aH[1], bH + half * 2);
                    mma_bf16(acc[0][nt], aH[0], bL + half * 2);
                    mma_bf16(acc[1][nt], aH[1], bL + half * 2);
                    mma_bf16(acc[0][nt], aL[0], bH + half * 2);
                    mma_bf16(acc[1][nt], aL[1], bH + half * 2);
                }
            }
        }
        __syncthreads();
        if (c + 2 < nCh) issue(c + 2, s);
        cp_commit();
    }

    const int r0 = m0 + wm * 32 + (lane >> 2);
    const int c0 = n0 + wn * (TN / 2) + (lane & 3) * 2;
    #pragma unroll
    for (int mt = 0; mt < 2; mt++) {
        #pragma unroll
        for (int nt = 0; nt < NT; nt++) {
            int col = c0 + nt * 8;
            float2 bv = make_float2(0.f, 0.f);
            if (bias) bv = *(const float2*)(bias + col);
            #pragma unroll
            for (int hrow = 0; hrow < 2; hrow++) {
                int row = r0 + mt * 16 + hrow * 8;
                float2 vv;
                vv.x = acc[mt][nt][hrow * 2 + 0] + bv.x;
                vv.y = acc[mt][nt][hrow * 2 + 1] + bv.y;
                size_t co = (size_t)row * ldc + col;
                if (res) {
                    float2 rr = *(const float2*)(res + co);
                    vv.x += rr.x; vv.y += rr.y;
                }
                if (act) {
                    vv.x = vv.x / (1.f + __expf(-1.702f * vv.x));
                    vv.y = vv.y / (1.f + __expf(-1.702f * vv.y));
                }
                if (Cf) {
                    *(float2*)(Cf + co) = vv;
                } else {
                    uint32_t ph, pll;
                    pack2(vv.x, vv.y, ph, pll);
                    *(uint32_t*)(Chi + co) = ph;
                    *(uint32_t*)(Clo + co) = pll;
                }
            }
        }
    }
}

// ======================= flash attention ====================================
// Grid: (1, T/128, 256). Block 256 (8 warps, 16 q-rows each, full 64 cols).
// smem: Q hi/lo 32KB, then 2 stages x (Kh 8K | Kl 8K | Vh 8K | Vl 8K).
#define FLASH_SMEM (32768 + 2 * 32768)
__global__ __launch_bounds__(256) void flash_kernel(
    const bf16* __restrict__ Qh, const bf16* __restrict__ Ql, int ldq,
    const bf16* __restrict__ Kh, const bf16* __restrict__ Kl, int ldk,
    const bf16* __restrict__ Vh, const bf16* __restrict__ Vl, int ldv,
    bf16* __restrict__ Oh, bf16* __restrict__ Ol, int S)
{
    extern __shared__ char dsm[];
    const uint32_t sQ  = smem_u32(dsm);
    const uint32_t sKV = sQ + 32768;
    const int tid = threadIdx.x, wid = tid >> 5, lane = tid & 31;
    const int z = blockIdx.z, b = z & 15, h = z >> 4;
    const int t0 = blockIdx.y * 128;
    const int hcol = h * 64;

    // Q tile (group 0 together with KV chunk 0)
    #pragma unroll
    for (int p = 0; p < 4; p++) {
        int idx = tid + (p << 8);
        int r = idx >> 3, q = idx & 7;
        uint32_t so = sQ + r * 128 + ((q ^ (r & 7)) << 4);
        size_t g = (size_t)((t0 + r) * BATCH + b) * ldq + hcol + q * 8;
        cp_async16(so,         Qh + g);
        cp_async16(so + 16384, Ql + g);
    }
    auto issue_kv = [&](int c, int st) {
        int s0 = c << 6;
        uint32_t sb = sKV + st * 32768;
        #pragma unroll
        for (int p = 0; p < 2; p++) {
            int idx = tid + (p << 8);
            int r = idx >> 3, q = idx & 7;
            uint32_t so = sb + r * 128 + ((q ^ (r & 7)) << 4);
            size_t rowg = (size_t)((s0 + r) * BATCH + b);
            size_t gk = rowg * ldk + hcol + q * 8;
            size_t gv = rowg * ldv + hcol + q * 8;
            cp_async16(so,         Kh + gk);
            cp_async16(so + 8192,  Kl + gk);
            cp_async16(so + 16384, Vh + gv);
            cp_async16(so + 24576, Vl + gv);
        }
    };
    issue_kv(0, 0); cp_commit();
    issue_kv(1, 1); cp_commit();

    float out[8][4];
    #pragma unroll
    for (int i = 0; i < 8; i++)
        #pragma unroll
        for (int j = 0; j < 4; j++) out[i][j] = 0.f;
    float mrow0 = -1e30f, mrow1 = -1e30f, lrow0 = 0.f, lrow1 = 0.f;

    const int nCh = S >> 6;
    for (int c = 0; c < nCh; c++) {
        cp_wait1();
        __syncthreads();
        const uint32_t sb = sKV + (c & 1) * 32768;

        // ---- scores: sc[128q x 64s] = Q . K^T (3-pass) ----
        float sc[8][4];
        #pragma unroll
        for (int i = 0; i < 8; i++)
            #pragma unroll
            for (int j = 0; j < 4; j++) sc[i][j] = 0.f;
        #pragma unroll
        for (int ks = 0; ks < 4; ks++) {
            uint32_t aH[4], aL[4];
            {
                int row = wid * 16 + (lane & 15);
                int cc  = 2 * ks + (lane >> 4);
                uint32_t off = row * 128 + ((cc ^ (row & 7)) << 4);
                ldsm4(aH, sQ + off);
                ldsm4(aL, sQ + 16384 + off);
            }
            #pragma unroll
            for (int ntp = 0; ntp < 4; ntp++) {
                int nrow = ntp * 16 + (lane & 7) + ((lane & 16) ? 8 : 0);
                int cc   = 2 * ks + ((lane >> 3) & 1);
                uint32_t off = nrow * 128 + ((cc ^ (nrow & 7)) << 4);
                uint32_t bH[4], bL[4];
                ldsm4(bH, sb + off);
                ldsm4(bL, sb + 8192 + off);
                #pragma unroll
                for (int half = 0; half < 2; half++) {
                    int nt = ntp * 2 + half;
                    mma_bf16(sc[nt], aH, bH + half * 2);
                    mma_bf16(sc[nt], aH, bL + half * 2);
                    mma_bf16(sc[nt], aL, bH + half * 2);
                }
            }
        }

        // ---- online softmax ----
        float mx0 = -1e30f, mx1 = -1e30f;
        #pragma unroll
        for (int nt = 0; nt < 8; nt++) {
            sc[nt][0] *= 0.125f; sc[nt][1] *= 0.125f;
            sc[nt][2] *= 0.125f; sc[nt][3] *= 0.125f;
            mx0 = fmaxf(mx0, fmaxf(sc[nt][0], sc[nt][1]));
            mx1 = fmaxf(mx1, fmaxf(sc[nt][2], sc[nt][3]));
        }
        mx0 = fmaxf(mx0, __shfl_xor_sync(~0u, mx0, 1));
        mx0 = fmaxf(mx0, __shfl_xor_sync(~0u, mx0, 2));
        mx1 = fmaxf(mx1, __shfl_xor_sync(~0u, mx1, 1));
        mx1 = fmaxf(mx1, __shfl_xor_sync(~0u, mx1, 2));
        float mn0 = fmaxf(mrow0, mx0), mn1 = fmaxf(mrow1, mx1);
        float cf0 = __expf(mrow0 - mn0), cf1 = __expf(mrow1 - mn1);
        mrow0 = mn0; mrow1 = mn1;
        float sum0 = 0.f, sum1 = 0.f;
        #pragma unroll
        for (int nt = 0; nt < 8; nt++) {
            sc[nt][0] = __expf(sc[nt][0] - mn0); sum0 += sc[nt][0];
            sc[nt][1] = __expf(sc[nt][1] - mn0); sum0 += sc[nt][1];
            sc[nt][2] = __expf(sc[nt][2] - mn1); sum1 += sc[nt][2];
            sc[nt][3] = __expf(sc[nt][3] - mn1); sum1 += sc[nt][3];
        }
        sum0 += __shfl_xor_sync(~0u, sum0, 1);
        sum0 += __shfl_xor_sync(~0u, sum0, 2);
        sum1 += __shfl_xor_sync(~0u, sum1, 1);
        sum1 += __shfl_xor_sync(~0u, sum1, 2);
        lrow0 = lrow0 * cf0 + sum0;
        lrow1 = lrow1 * cf1 + sum1;
        #pragma unroll
        for (int nt = 0; nt < 8; nt++) {
            out[nt][0] *= cf0; out[nt][1] *= cf0;
            out[nt][2] *= cf1; out[nt][3] *= cf1;
        }

        // ---- PV: out += P . V (3-pass, V^T via ldmatrix.trans) ----
        #pragma unroll
        for (int t = 0; t < 4; t++) {
            uint32_t aPh[4], aPl[4];
            pack2(sc[2*t][0],   sc[2*t][1],   aPh[0], aPl[0]);
            pack2(sc[2*t][2],   sc[2*t][3],   aPh[1], aPl[1]);
            pack2(sc[2*t+1][0], sc[2*t+1][1], aPh[2], aPl[2]);
            pack2(sc[2*t+1][2], sc[2*t+1][3], aPh[3], aPl[3]);
            #pragma unroll
            for (int ntp = 0; ntp < 4; ntp++) {
                int row = 16 * t + (lane & 7) + ((lane & 8) ? 8 : 0);
                int cc  = 2 * ntp + (lane >> 4);
                uint32_t off = row * 128 + ((cc ^ (row & 7)) << 4);
                uint32_t bH[4], bL[4];
                ldsm4t(bH, sb + 16384 + off);
                ldsm4t(bL, sb + 24576 + off);
                #pragma unroll
                for (int half = 0; half < 2; half++) {
                    int nt = ntp * 2 + half;
                    mma_bf16(out[nt], aPh, bH + half * 2);
                    mma_bf16(out[nt], aPh, bL + half * 2);
                    mma_bf16(out[nt], aPl, bH + half * 2);
                }
            }
        }
        __syncthreads();
        if (c + 2 < nCh) issue_kv(c + 2, c & 1);
        cp_commit();
    }

    // ---- epilogue: normalize + split store ----
    float inv0 = 1.f / lrow0, inv1 = 1.f / lrow1;
    int trow0 = t0 + wid * 16 + (lane >> 2);
    size_t gr0 = (size_t)(trow0 * BATCH + b) * D_MODEL;
    size_t gr1 = (size_t)((trow0 + 8) * BATCH + b) * D_MODEL;
    #pragma unroll
    for (int nt = 0; nt < 8; nt++) {
        int col = hcol + nt * 8 + (lane & 3) * 2;
        uint32_t ph, pl;
        pack2(out[nt][0] * inv0, out[nt][1] * inv0, ph, pl);
        *(uint32_t*)(Oh + gr0 + col) = ph;
        *(uint32_t*)(Ol + gr0 + col) = pl;
        pack2(out[nt][2] * inv1, out[nt][3] * inv1, ph, pl);
        *(uint32_t*)(Oh + gr1 + col) = ph;
        *(uint32_t*)(Ol + gr1 + col) = pl;
    }
}

// ---------------- split fp32 -> bf16 hi/lo -----------------------------------
__global__ __launch_bounds__(256) void split_kernel(
    const float4* __restrict__ src, uint32_t* __restrict__ hi,
    uint32_t* __restrict__ lo)
{
    size_t i = (size_t)blockIdx.x * 256 + threadIdx.x;
    float4 v = src[i];
    uint32_t h0, l0, h1, l1;
    pack2(v.x, v.y, h0, l0);
    pack2(v.z, v.w, h1, l1);
    hi[i * 2] = h0; hi[i * 2 + 1] = h1;
    lo[i * 2] = l0; lo[i * 2 + 1] = l1;
}

// ---------------- LayerNorm -> split bf16 ------------------------------------
__global__ __launch_bounds__(256) void ln_split_kernel(
    const float* __restrict__ x, const float* __restrict__ g,
    const float* __restrict__ b, bf16* __restrict__ yh, bf16* __restrict__ yl)
{
    int row = blockIdx.x;
    const float4* xr = (const float4*)(x + (size_t)row * D_MODEL);
    int tid = threadIdx.x;
    float4 v = xr[tid];
    float s  = v.x + v.y + v.z + v.w;
    float ss = v.x*v.x + v.y*v.y + v.z*v.z + v.w*v.w;
    #pragma unroll
    for (int o = 16; o; o >>= 1) {
        s  += __shfl_xor_sync(~0u, s,  o);
        ss += __shfl_xor_sync(~0u, ss, o);
    }
    __shared__ float smS[8], smSS[8];
    int w = tid >> 5;
    if ((tid & 31) == 0) { smS[w] = s; smSS[w] = ss; }
    __syncthreads();
    if (tid < 32) {
        s  = (tid < 8) ? smS[tid]  : 0.f;
        ss = (tid < 8) ? smSS[tid] : 0.f;
        #pragma unroll
        for (int o = 4; o; o >>= 1) {
            s  += __shfl_xor_sync(~0u, s,  o);
            ss += __shfl_xor_sync(~0u, ss, o);
        }
        if (tid == 0) { smS[0] = s; smSS[0] = ss; }
    }
    __syncthreads();
    float mean = smS[0] * (1.f / D_MODEL);
    float var  = smSS[0] * (1.f / D_MODEL) - mean * mean;
    float rstd = rsqrtf(var + 1e-5f);
    float4 gv = ((const float4*)g)[tid];
    float4 bv = ((const float4*)b)[tid];
    float4 o;
    o.x = (v.x - mean) * rstd * gv.x + bv.x;
    o.y = (v.y - mean) * rstd * gv.y + bv.y;
    o.z = (v.z - mean) * rstd * gv.z + bv.z;
    o.w = (v.w - mean) * rstd * gv.w + bv.w;
    uint32_t h0, l0, h1, l1;
    pack2(o.x, o.y, h0, l0);
    pack2(o.z, o.w, h1, l1);
    uint32_t* yhr = (uint32_t*)(yh + (size_t)row * D_MODEL);
    uint32_t* ylr = (uint32_t*)(yl + (size_t)row * D_MODEL);
    yhr[tid * 2] = h0; yhr[tid * 2 + 1] = h1;
    ylr[tid * 2] = l0; ylr[tid * 2 + 1] = l1;
}

// ---------------- orchestration ---------------------------------------------
extern "C" void kernel_launch(void* const* d_in, const int* in_sizes, int n_in,
                              void* d_out, int out_size)
{
    const float* x        = (const float*)d_in[0];
    const float* hid      = (const float*)d_in[1];
    const float* ln1_g    = (const float*)d_in[2];
    const float* ln1_b    = (const float*)d_in[3];
    const float* sa_in_w  = (const float*)d_in[4];
    const float* sa_in_b  = (const float*)d_in[5];
    const float* sa_out_w = (const float*)d_in[6];
    const float* sa_out_b = (const float*)d_in[7];
    const float* ln2_g    = (const float*)d_in[8];
    const float* ln2_b    = (const float*)d_in[9];
    const float* ca_in_w  = (const float*)d_in[10];
    const float* ca_in_b  = (const float*)d_in[11];
    const float* ca_out_w = (const float*)d_in[12];
    const float* ca_out_b = (const float*)d_in[13];
    const float* ln3_g    = (const float*)d_in[14];
    const float* ln3_b    = (const float*)d_in[15];
    const float* fc_w     = (const float*)d_in[16];
    const float* fc_b     = (const float*)d_in[17];
    const float* proj_w   = (const float*)d_in[18];
    const float* proj_b   = (const float*)d_in[19];
    float* out = (float*)d_out;

    bf16 *whi, *wlo, *hidh, *hidl, *hh, *hl, *qkvh, *qkvl, *kvh, *kvl;
    bf16 *ctxh, *ctxl, *ffnh, *ffnl;
    cudaGetSymbolAddress((void**)&whi,  g_w_hi);
    cudaGetSymbolAddress((void**)&wlo,  g_w_lo);
    cudaGetSymbolAddress((void**)&hidh, g_hid_hi);
    cudaGetSymbolAddress((void**)&hidl, g_hid_lo);
    cudaGetSymbolAddress((void**)&hh,   g_h_hi);
    cudaGetSymbolAddress((void**)&hl,   g_h_lo);
    cudaGetSymbolAddress((void**)&qkvh, g_qkv_hi);
    cudaGetSymbolAddress((void**)&qkvl, g_qkv_lo);
    cudaGetSymbolAddress((void**)&kvh,  g_kv_hi);
    cudaGetSymbolAddress((void**)&kvl,  g_kv_lo);
    cudaGetSymbolAddress((void**)&ctxh, g_ctx_hi);
    cudaGetSymbolAddress((void**)&ctxl, g_ctx_lo);
    cudaGetSymbolAddress((void**)&ffnh, g_ffn_hi);
    cudaGetSymbolAddress((void**)&ffnl, g_ffn_lo);

    const int SM128 = 65536;
    cudaFuncSetAttribute(gemm_bf16<128>,
                         cudaFuncAttributeMaxDynamicSharedMemorySize, SM128);
    cudaFuncSetAttribute(flash_kernel,
                         cudaFuncAttributeMaxDynamicSharedMemorySize, FLASH_SMEM);

    // ---- one-time splits ----
    split_kernel<<<3072, 256>>>((const float4*)sa_in_w,
        (uint32_t*)(whi + WS_SA_IN), (uint32_t*)(wlo + WS_SA_IN));
    split_kernel<<<1024, 256>>>((const float4*)sa_out_w,
        (uint32_t*)(whi + WS_SA_OUT), (uint32_t*)(wlo + WS_SA_OUT));
    split_kernel<<<3072, 256>>>((const float4*)ca_in_w,
        (uint32_t*)(whi + WS_CA_IN), (uint32_t*)(wlo + WS_CA_IN));
    split_kernel<<<1024, 256>>>((const float4*)ca_out_w,
        (uint32_t*)(whi + WS_CA_OUT), (uint32_t*)(wlo + WS_CA_OUT));
    split_kernel<<<4096, 256>>>((const float4*)fc_w,
        (uint32_t*)(whi + WS_FC), (uint32_t*)(wlo + WS_FC));
    split_kernel<<<4096, 256>>>((const float4*)proj_w,
        (uint32_t*)(whi + WS_PROJ), (uint32_t*)(wlo + WS_PROJ));
    split_kernel<<<16384, 256>>>((const float4*)hid,
        (uint32_t*)hidh, (uint32_t*)hidl);

    // ================= self attention =================
    ln_split_kernel<<<MQ, 256>>>(x, ln1_g, ln1_b, hh, hl);
    gemm_bf16<128><<<dim3(24, 64, 1), 256, SM128>>>(
        hh, hl, 1024, whi + WS_SA_IN, wlo + WS_SA_IN, 1024,
        sa_in_b, nullptr, nullptr, qkvh, qkvl, 3072, 1024, 0);
    flash_kernel<<<dim3(1, 4, 256), 256, FLASH_SMEM>>>(
        qkvh, qkvl, 3072,
        qkvh + 1024, qkvl + 1024, 3072,
        qkvh + 2048, qkvl + 2048, 3072,
        ctxh, ctxl, T_LEN);
    gemm_bf16<128><<<dim3(8, 64, 1), 256, SM128>>>(
        ctxh, ctxl, 1024, whi + WS_SA_OUT, wlo + WS_SA_OUT, 1024,
        sa_out_b, x, out, nullptr, nullptr, 1024, 1024, 0);

    // ================= cross attention =================
    ln_split_kernel<<<MQ, 256>>>(out, ln2_g, ln2_b, hh, hl);
    gemm_bf16<128><<<dim3(8, 64, 1), 256, SM128>>>(
        hh, hl, 1024, whi + WS_CA_IN, wlo + WS_CA_IN, 1024,
        ca_in_b, nullptr, nullptr, qkvh, qkvl, 1024, 1024, 0);
    gemm_bf16<128><<<dim3(16, 128, 1), 256, SM128>>>(
        hidh, hidl, 1024,
        whi + WS_CA_IN + 1048576, wlo + WS_CA_IN + 1048576, 1024,
        ca_in_b + 1024, nullptr, nullptr, kvh, kvl, 2048, 1024, 0);
    flash_kernel<<<dim3(1, 4, 256), 256, FLASH_SMEM>>>(
        qkvh, qkvl, 1024,
        kvh, kvl, 2048,
        kvh + 1024, kvl + 1024, 2048,
        ctxh, ctxl, S_LEN);
    gemm_bf16<128><<<dim3(8, 64, 1), 256, SM128>>>(
        ctxh, ctxl, 1024, whi + WS_CA_OUT, wlo + WS_CA_OUT, 1024,
        ca_out_b, out, out, nullptr, nullptr, 1024, 1024, 0);

    // ================= MLP =================
    ln_split_kernel<<<MQ, 256>>>(out, ln3_g, ln3_b, hh, hl);
    gemm_bf16<128><<<dim3(32, 64, 1), 256, SM128>>>(
        hh, hl, 1024, whi + WS_FC, wlo + WS_FC, 1024,
        fc_b, nullptr, nullptr, ffnh, ffnl, 4096, 1024, 1);
    gemm_bf16<128><<<dim3(8, 64, 1), 256, SM128>>>(
        ffnh, ffnl, 4096, whi + WS_PROJ, wlo + WS_PROJ, 4096,
        proj_b, out, out, nullptr, nullptr, 1024, 4096, 0);
}

// round 7
// speedup vs baseline: 6.3765x; 1.3197x over previous
#include <cuda_runtime.h>
#include <cuda_bf16.h>
#include <math.h>
#include <stdint.h>

#define D_MODEL 1024
#define N_HEAD  16
#define T_LEN   512
#define S_LEN   1024
#define BATCH   16
#define MQ      (T_LEN * BATCH)   /* 8192  query rows  */
#define MKV     (S_LEN * BATCH)   /* 16384 kv rows     */
typedef __nv_bfloat16 bf16;

// ---------------- scratch (static device globals; no allocation) ------------
#define WS_SA_IN  0u
#define WS_SA_OUT (3u*1024*1024)
#define WS_CA_IN  (4u*1024*1024)
#define WS_CA_OUT (7u*1024*1024)
#define WS_FC     (8u*1024*1024)
#define WS_PROJ   (12u*1024*1024)
#define WS_TOTAL  (16u*1024*1024)
__device__ float g_w  [WS_TOTAL];             // tf32-rounded weights
__device__ float g_hid[MKV * D_MODEL];        // tf32-rounded hidden_states
__device__ float g_h  [MQ * D_MODEL];         // LN output (tf32-rounded)
__device__ bf16  g_qkv_hi[MQ*3*D_MODEL],  g_qkv_lo[MQ*3*D_MODEL];
__device__ bf16  g_kv_hi[MKV*2*D_MODEL],  g_kv_lo[MKV*2*D_MODEL];
__device__ float g_ctx[MQ * D_MODEL];         // flash output (tf32-rounded)
__device__ float g_ffn[MQ * 4 * D_MODEL];     // MLP hidden (tf32-rounded)

__device__ __forceinline__ uint32_t b2u(__nv_bfloat162 x) {
    return *reinterpret_cast<uint32_t*>(&x);
}
__device__ __forceinline__ float rna(float x) {
    uint32_t u;
    asm("cvt.rna.tf32.f32 %0, %1;" : "=r"(u) : "f"(x));
    return __uint_as_float(u);
}
__device__ __forceinline__ uint32_t smem_u32(const void* p) {
    uint32_t a;
    asm("{ .reg .u64 t; cvta.to.shared.u64 t, %1; cvt.u32.u64 %0, t; }"
        : "=r"(a) : "l"(p));
    return a;
}
__device__ __forceinline__ void cp_async16(uint32_t s, const void* g) {
    asm volatile("cp.async.cg.shared.global [%0], [%1], 16;" :: "r"(s), "l"(g));
}
__device__ __forceinline__ void cp_commit() {
    asm volatile("cp.async.commit_group;");
}
__device__ __forceinline__ void cp_wait1() {
    asm volatile("cp.async.wait_group 1;");
}
__device__ __forceinline__ void ldsm4(uint32_t* r, uint32_t addr) {
    asm volatile("ldmatrix.sync.aligned.m8n8.x4.shared.b16 {%0,%1,%2,%3}, [%4];"
                 : "=r"(r[0]), "=r"(r[1]), "=r"(r[2]), "=r"(r[3]) : "r"(addr));
}
__device__ __forceinline__ void ldsm4t(uint32_t* r, uint32_t addr) {
    asm volatile("ldmatrix.sync.aligned.m8n8.x4.trans.shared.b16 {%0,%1,%2,%3}, [%4];"
                 : "=r"(r[0]), "=r"(r[1]), "=r"(r[2]), "=r"(r[3]) : "r"(addr));
}
__device__ __forceinline__ void mma_bf16(float* c, const uint32_t* a,
                                         const uint32_t* b) {
    asm volatile(
        "mma.sync.aligned.m16n8k16.row.col.f32.bf16.bf16.f32 "
        "{%0,%1,%2,%3}, {%4,%5,%6,%7}, {%8,%9}, {%0,%1,%2,%3};"
        : "+f"(c[0]), "+f"(c[1]), "+f"(c[2]), "+f"(c[3])
        : "r"(a[0]), "r"(a[1]), "r"(a[2]), "r"(a[3]),
          "r"(b[0]), "r"(b[1]));
}
__device__ __forceinline__ void mma_tf32(float* c, const uint32_t* a,
                                         const uint32_t* b) {
    asm volatile(
        "mma.sync.aligned.m16n8k8.row.col.f32.tf32.tf32.f32 "
        "{%0,%1,%2,%3}, {%4,%5,%6,%7}, {%8,%9}, {%0,%1,%2,%3};"
        : "+f"(c[0]), "+f"(c[1]), "+f"(c[2]), "+f"(c[3])
        : "r"(a[0]), "r"(a[1]), "r"(a[2]), "r"(a[3]),
          "r"(b[0]), "r"(b[1]));
}
__device__ __forceinline__ void pack2(float x, float y,
                                      uint32_t& hi, uint32_t& lo) {
    __nv_bfloat162 h = __floats2bfloat162_rn(x, y);
    float2 f = __bfloat1622float2(h);
    __nv_bfloat162 l = __floats2bfloat162_rn(x - f.x, y - f.y);
    hi = b2u(h); lo = b2u(l);
}

// ======================= TF32 single-pass GEMM ==============================
// C[m,n] = sum_k A[m,k]*B[n,k], fp32 operands pre-rounded to tf32 (RNA).
// Tile 128x128, BK=32 (128B rows, 16B-chunk XOR swizzle), 2-stage cp.async,
// ldmatrix fragments. 8 warps 4x2. act=1: quickGELU + RNA-round output.
__global__ __launch_bounds__(256, 2) void gemm_tf32(
    const float* __restrict__ A, int lda,
    const float* __restrict__ B, int ldb,
    const float* __restrict__ bias,
    const float* __restrict__ res,
    float* __restrict__ Cf, bf16* __restrict__ Chi, bf16* __restrict__ Clo,
    int ldc, int K, int act)
{
    extern __shared__ char dsm[];
    const uint32_t smem_base = smem_u32(dsm);
    const int tid = threadIdx.x, wid = tid >> 5, lane = tid & 31;
    const int wm = wid >> 1, wn = wid & 1;
    const int m0 = blockIdx.y * 128, n0 = blockIdx.x * 128;

    float acc[2][8][4];
    #pragma unroll
    for (int i = 0; i < 2; i++)
        #pragma unroll
        for (int j = 0; j < 8; j++)
            #pragma unroll
            for (int q = 0; q < 4; q++) acc[i][j][q] = 0.f;

    const int nCh = K >> 5;
    auto issue = [&](int c, int s) {
        const int k0 = c << 5;
        const uint32_t sb = smem_base + s * 32768;
        #pragma unroll
        for (int it = 0; it < 4; it++) {
            int idx = tid + (it << 8);
            int r = idx >> 3, q = idx & 7;
            uint32_t so = sb + r * 128 + ((q ^ (r & 7)) << 4);
            cp_async16(so, A + (size_t)(m0 + r) * lda + k0 + q * 4);
        }
        #pragma unroll
        for (int it = 0; it < 4; it++) {
            int idx = tid + (it << 8);
            int r = idx >> 3, q = idx & 7;
            uint32_t so = sb + 16384 + r * 128 + ((q ^ (r & 7)) << 4);
            cp_async16(so, B + (size_t)(n0 + r) * ldb + k0 + q * 4);
        }
    };

    issue(0, 0); cp_commit();
    issue(1, 1); cp_commit();

    for (int c = 0; c < nCh; c++) {
        const int s = c & 1;
        cp_wait1();
        __syncthreads();
        const uint32_t sb = smem_base + s * 32768;
        #pragma unroll
        for (int ks = 0; ks < 4; ks++) {
            uint32_t a[2][4];
            #pragma unroll
            for (int mt = 0; mt < 2; mt++) {
                int row = wm * 32 + mt * 16 + (lane & 15);
                int q   = 2 * ks + (lane >> 4);
                ldsm4(a[mt], sb + row * 128 + ((q ^ (row & 7)) << 4));
            }
            #pragma unroll
            for (int ntp = 0; ntp < 4; ntp++) {
                int nrow = wn * 64 + ntp * 16 + (lane & 7)
                         + ((lane & 16) ? 8 : 0);
                int q    = 2 * ks + ((lane >> 3) & 1);
                uint32_t b[4];
                ldsm4(b, sb + 16384 + nrow * 128 + ((q ^ (nrow & 7)) << 4));
                #pragma unroll
                for (int half = 0; half < 2; half++) {
                    int nt = ntp * 2 + half;
                    mma_tf32(acc[0][nt], a[0], b + half * 2);
                    mma_tf32(acc[1][nt], a[1], b + half * 2);
                }
            }
        }
        __syncthreads();
        if (c + 2 < nCh) issue(c + 2, s);
        cp_commit();
    }

    const int r0 = m0 + wm * 32 + (lane >> 2);
    const int c0 = n0 + wn * 64 + (lane & 3) * 2;
    #pragma unroll
    for (int mt = 0; mt < 2; mt++) {
        #pragma unroll
        for (int nt = 0; nt < 8; nt++) {
            int col = c0 + nt * 8;
            float2 bv = make_float2(0.f, 0.f);
            if (bias) bv = *(const float2*)(bias + col);
            #pragma unroll
            for (int hrow = 0; hrow < 2; hrow++) {
                int row = r0 + mt * 16 + hrow * 8;
                float2 vv;
                vv.x = acc[mt][nt][hrow * 2 + 0] + bv.x;
                vv.y = acc[mt][nt][hrow * 2 + 1] + bv.y;
                size_t co = (size_t)row * ldc + col;
                if (res) {
                    float2 rr = *(const float2*)(res + co);
                    vv.x += rr.x; vv.y += rr.y;
                }
                if (act) {
                    vv.x = rna(vv.x / (1.f + __expf(-1.702f * vv.x)));
                    vv.y = rna(vv.y / (1.f + __expf(-1.702f * vv.y)));
                }
                if (Cf) {
                    *(float2*)(Cf + co) = vv;
                } else {
                    uint32_t ph, pll;
                    pack2(vv.x, vv.y, ph, pll);
                    *(uint32_t*)(Chi + co) = ph;
                    *(uint32_t*)(Clo + co) = pll;
                }
            }
        }
    }
}

// ======================= flash attention (bf16 3-pass) ======================
#define FLASH_SMEM (32768 + 2 * 32768)
__global__ __launch_bounds__(256) void flash_kernel(
    const bf16* __restrict__ Qh, const bf16* __restrict__ Ql, int ldq,
    const bf16* __restrict__ Kh, const bf16* __restrict__ Kl, int ldk,
    const bf16* __restrict__ Vh, const bf16* __restrict__ Vl, int ldv,
    float* __restrict__ O, int S)
{
    extern __shared__ char dsm[];
    const uint32_t sQ  = smem_u32(dsm);
    const uint32_t sKV = sQ + 32768;
    const int tid = threadIdx.x, wid = tid >> 5, lane = tid & 31;
    const int z = blockIdx.z, b = z & 15, h = z >> 4;
    const int t0 = blockIdx.y * 128;
    const int hcol = h * 64;

    #pragma unroll
    for (int p = 0; p < 4; p++) {
        int idx = tid + (p << 8);
        int r = idx >> 3, q = idx & 7;
        uint32_t so = sQ + r * 128 + ((q ^ (r & 7)) << 4);
        size_t g = (size_t)((t0 + r) * BATCH + b) * ldq + hcol + q * 8;
        cp_async16(so,         Qh + g);
        cp_async16(so + 16384, Ql + g);
    }
    auto issue_kv = [&](int c, int st) {
        int s0 = c << 6;
        uint32_t sb = sKV + st * 32768;
        #pragma unroll
        for (int p = 0; p < 2; p++) {
            int idx = tid + (p << 8);
            int r = idx >> 3, q = idx & 7;
            uint32_t so = sb + r * 128 + ((q ^ (r & 7)) << 4);
            size_t rowg = (size_t)((s0 + r) * BATCH + b);
            size_t gk = rowg * ldk + hcol + q * 8;
            size_t gv = rowg * ldv + hcol + q * 8;
            cp_async16(so,         Kh + gk);
            cp_async16(so + 8192,  Kl + gk);
            cp_async16(so + 16384, Vh + gv);
            cp_async16(so + 24576, Vl + gv);
        }
    };
    issue_kv(0, 0); cp_commit();
    issue_kv(1, 1); cp_commit();

    float out[8][4];
    #pragma unroll
    for (int i = 0; i < 8; i++)
        #pragma unroll
        for (int j = 0; j < 4; j++) out[i][j] = 0.f;
    float mrow0 = -1e30f, mrow1 = -1e30f, lrow0 = 0.f, lrow1 = 0.f;

    const int nCh = S >> 6;
    for (int c = 0; c < nCh; c++) {
        cp_wait1();
        __syncthreads();
        const uint32_t sb = sKV + (c & 1) * 32768;

        float sc[8][4];
        #pragma unroll
        for (int i = 0; i < 8; i++)
            #pragma unroll
            for (int j = 0; j < 4; j++) sc[i][j] = 0.f;
        #pragma unroll
        for (int ks = 0; ks < 4; ks++) {
            uint32_t aH[4], aL[4];
            {
                int row = wid * 16 + (lane & 15);
                int cc  = 2 * ks + (lane >> 4);
                uint32_t off = row * 128 + ((cc ^ (row & 7)) << 4);
                ldsm4(aH, sQ + off);
                ldsm4(aL, sQ + 16384 + off);
            }
            #pragma unroll
            for (int ntp = 0; ntp < 4; ntp++) {
                int nrow = ntp * 16 + (lane & 7) + ((lane & 16) ? 8 : 0);
                int cc   = 2 * ks + ((lane >> 3) & 1);
                uint32_t off = nrow * 128 + ((cc ^ (nrow & 7)) << 4);
                uint32_t bH[4], bL[4];
                ldsm4(bH, sb + off);
                ldsm4(bL, sb + 8192 + off);
                #pragma unroll
                for (int half = 0; half < 2; half++) {
                    int nt = ntp * 2 + half;
                    mma_bf16(sc[nt], aH, bH + half * 2);
                    mma_bf16(sc[nt], aH, bL + half * 2);
                    mma_bf16(sc[nt], aL, bH + half * 2);
                }
            }
        }

        float mx0 = -1e30f, mx1 = -1e30f;
        #pragma unroll
        for (int nt = 0; nt < 8; nt++) {
            sc[nt][0] *= 0.125f; sc[nt][1] *= 0.125f;
            sc[nt][2] *= 0.125f; sc[nt][3] *= 0.125f;
            mx0 = fmaxf(mx0, fmaxf(sc[nt][0], sc[nt][1]));
            mx1 = fmaxf(mx1, fmaxf(sc[nt][2], sc[nt][3]));
        }
        mx0 = fmaxf(mx0, __shfl_xor_sync(~0u, mx0, 1));
        mx0 = fmaxf(mx0, __shfl_xor_sync(~0u, mx0, 2));
        mx1 = fmaxf(mx1, __shfl_xor_sync(~0u, mx1, 1));
        mx1 = fmaxf(mx1, __shfl_xor_sync(~0u, mx1, 2));
        float mn0 = fmaxf(mrow0, mx0), mn1 = fmaxf(mrow1, mx1);
        float cf0 = __expf(mrow0 - mn0), cf1 = __expf(mrow1 - mn1);
        mrow0 = mn0; mrow1 = mn1;
        float sum0 = 0.f, sum1 = 0.f;
        #pragma unroll
        for (int nt = 0; nt < 8; nt++) {
            sc[nt][0] = __expf(sc[nt][0] - mn0); sum0 += sc[nt][0];
            sc[nt][1] = __expf(sc[nt][1] - mn0); sum0 += sc[nt][1];
            sc[nt][2] = __expf(sc[nt][2] - mn1); sum1 += sc[nt][2];
            sc[nt][3] = __expf(sc[nt][3] - mn1); sum1 += sc[nt][3];
        }
        sum0 += __shfl_xor_sync(~0u, sum0, 1);
        sum0 += __shfl_xor_sync(~0u, sum0, 2);
        sum1 += __shfl_xor_sync(~0u, sum1, 1);
        sum1 += __shfl_xor_sync(~0u, sum1, 2);
        lrow0 = lrow0 * cf0 + sum0;
        lrow1 = lrow1 * cf1 + sum1;
        #pragma unroll
        for (int nt = 0; nt < 8; nt++) {
            out[nt][0] *= cf0; out[nt][1] *= cf0;
            out[nt][2] *= cf1; out[nt][3] *= cf1;
        }

        #pragma unroll
        for (int t = 0; t < 4; t++) {
            uint32_t aPh[4], aPl[4];
            pack2(sc[2*t][0],   sc[2*t][1],   aPh[0], aPl[0]);
            pack2(sc[2*t][2],   sc[2*t][3],   aPh[1], aPl[1]);
            pack2(sc[2*t+1][0], sc[2*t+1][1], aPh[2], aPl[2]);
            pack2(sc[2*t+1][2], sc[2*t+1][3], aPh[3], aPl[3]);
            #pragma unroll
            for (int ntp = 0; ntp < 4; ntp++) {
                int row = 16 * t + (lane & 7) + ((lane & 8) ? 8 : 0);
                int cc  = 2 * ntp + (lane >> 4);
                uint32_t off = row * 128 + ((cc ^ (row & 7)) << 4);
                uint32_t bH[4], bL[4];
                ldsm4t(bH, sb + 16384 + off);
                ldsm4t(bL, sb + 24576 + off);
                #pragma unroll
                for (int half = 0; half < 2; half++) {
                    int nt = ntp * 2 + half;
                    mma_bf16(out[nt], aPh, bH + half * 2);
                    mma_bf16(out[nt], aPh, bL + half * 2);
                    mma_bf16(out[nt], aPl, bH + half * 2);
                }
            }
        }
        __syncthreads();
        if (c + 2 < nCh) issue_kv(c + 2, c & 1);
        cp_commit();
    }

    float inv0 = 1.f / lrow0, inv1 = 1.f / lrow1;
    int trow0 = t0 + wid * 16 + (lane >> 2);
    size_t gr0 = (size_t)(trow0 * BATCH + b) * D_MODEL;
    size_t gr1 = (size_t)((trow0 + 8) * BATCH + b) * D_MODEL;
    #pragma unroll
    for (int nt = 0; nt < 8; nt++) {
        int col = hcol + nt * 8 + (lane & 3) * 2;
        *(float2*)(O + gr0 + col) =
            make_float2(rna(out[nt][0] * inv0), rna(out[nt][1] * inv0));
        *(float2*)(O + gr1 + col) =
            make_float2(rna(out[nt][2] * inv1), rna(out[nt][3] * inv1));
    }
}

// ---------------- RNA tf32-round convert -------------------------------------
__global__ __launch_bounds__(256) void cvt_kernel(
    const float4* __restrict__ src, float4* __restrict__ dst)
{
    size_t i = (size_t)blockIdx.x * 256 + threadIdx.x;
    float4 v = src[i];
    dst[i] = make_float4(rna(v.x), rna(v.y), rna(v.z), rna(v.w));
}

// ---------------- LayerNorm -> RNA tf32 fp32 ---------------------------------
__global__ __launch_bounds__(256) void ln_kernel(
    const float* __restrict__ x, const float* __restrict__ g,
    const float* __restrict__ b, float* __restrict__ y)
{
    int row = blockIdx.x;
    const float4* xr = (const float4*)(x + (size_t)row * D_MODEL);
    int tid = threadIdx.x;
    float4 v = xr[tid];
    float s  = v.x + v.y + v.z + v.w;
    float ss = v.x*v.x + v.y*v.y + v.z*v.z + v.w*v.w;
    #pragma unroll
    for (int o = 16; o; o >>= 1) {
        s  += __shfl_xor_sync(~0u, s,  o);
        ss += __shfl_xor_sync(~0u, ss, o);
    }
    __shared__ float smS[8], smSS[8];
    int w = tid >> 5;
    if ((tid & 31) == 0) { smS[w] = s; smSS[w] = ss; }
    __syncthreads();
    if (tid < 32) {
        s  = (tid < 8) ? smS[tid]  : 0.f;
        ss = (tid < 8) ? smSS[tid] : 0.f;
        #pragma unroll
        for (int o = 4; o; o >>= 1) {
            s  += __shfl_xor_sync(~0u, s,  o);
            ss += __shfl_xor_sync(~0u, ss, o);
        }
        if (tid == 0) { smS[0] = s; smSS[0] = ss; }
    }
    __syncthreads();
    float mean = smS[0] * (1.f / D_MODEL);
    float var  = smSS[0] * (1.f / D_MODEL) - mean * mean;
    float rstd = rsqrtf(var + 1e-5f);
    float4 gv = ((const float4*)g)[tid];
    float4 bv = ((const float4*)b)[tid];
    float4 o;
    o.x = rna((v.x - mean) * rstd * gv.x + bv.x);
    o.y = rna((v.y - mean) * rstd * gv.y + bv.y);
    o.z = rna((v.z - mean) * rstd * gv.z + bv.z);
    o.w = rna((v.w - mean) * rstd * gv.w + bv.w);
    ((float4*)(y + (size_t)row * D_MODEL))[tid] = o;
}

// ---------------- orchestration ---------------------------------------------
extern "C" void kernel_launch(void* const* d_in, const int* in_sizes, int n_in,
                              void* d_out, int out_size)
{
    const float* x        = (const float*)d_in[0];
    const float* hid      = (const float*)d_in[1];
    const float* ln1_g    = (const float*)d_in[2];
    const float* ln1_b    = (const float*)d_in[3];
    const float* sa_in_w  = (const float*)d_in[4];
    const float* sa_in_b  = (const float*)d_in[5];
    const float* sa_out_w = (const float*)d_in[6];
    const float* sa_out_b = (const float*)d_in[7];
    const float* ln2_g    = (const float*)d_in[8];
    const float* ln2_b    = (const float*)d_in[9];
    const float* ca_in_w  = (const float*)d_in[10];
    const float* ca_in_b  = (const float*)d_in[11];
    const float* ca_out_w = (const float*)d_in[12];
    const float* ca_out_b = (const float*)d_in[13];
    const float* ln3_g    = (const float*)d_in[14];
    const float* ln3_b    = (const float*)d_in[15];
    const float* fc_w     = (const float*)d_in[16];
    const float* fc_b     = (const float*)d_in[17];
    const float* proj_w   = (const float*)d_in[18];
    const float* proj_b   = (const float*)d_in[19];
    float* out = (float*)d_out;

    float *w, *hidc, *h, *ctx, *ffn;
    bf16 *qkvh, *qkvl, *kvh, *kvl;
    cudaGetSymbolAddress((void**)&w,    g_w);
    cudaGetSymbolAddress((void**)&hidc, g_hid);
    cudaGetSymbolAddress((void**)&h,    g_h);
    cudaGetSymbolAddress((void**)&qkvh, g_qkv_hi);
    cudaGetSymbolAddress((void**)&qkvl, g_qkv_lo);
    cudaGetSymbolAddress((void**)&kvh,  g_kv_hi);
    cudaGetSymbolAddress((void**)&kvl,  g_kv_lo);
    cudaGetSymbolAddress((void**)&ctx,  g_ctx);
    cudaGetSymbolAddress((void**)&ffn,  g_ffn);

    const int SMG = 65536;
    cudaFuncSetAttribute(gemm_tf32,
                         cudaFuncAttributeMaxDynamicSharedMemorySize, SMG);
    cudaFuncSetAttribute(flash_kernel,
                         cudaFuncAttributeMaxDynamicSharedMemorySize, FLASH_SMEM);

    // ---- one-time tf32 rounding of weights + hidden ----
    cvt_kernel<<<3072, 256>>>((const float4*)sa_in_w,  (float4*)(w + WS_SA_IN));
    cvt_kernel<<<1024, 256>>>((const float4*)sa_out_w, (float4*)(w + WS_SA_OUT));
    cvt_kernel<<<3072, 256>>>((const float4*)ca_in_w,  (float4*)(w + WS_CA_IN));
    cvt_kernel<<<1024, 256>>>((const float4*)ca_out_w, (float4*)(w + WS_CA_OUT));
    cvt_kernel<<<4096, 256>>>((const float4*)fc_w,     (float4*)(w + WS_FC));
    cvt_kernel<<<4096, 256>>>((const float4*)proj_w,   (float4*)(w + WS_PROJ));
    cvt_kernel<<<16384, 256>>>((const float4*)hid,     (float4*)hidc);

    // ================= self attention =================
    ln_kernel<<<MQ, 256>>>(x, ln1_g, ln1_b, h);
    gemm_tf32<<<dim3(24, 64), 256, SMG>>>(
        h, 1024, w + WS_SA_IN, 1024,
        sa_in_b, nullptr, nullptr, qkvh, qkvl, 3072, 1024, 0);
    flash_kernel<<<dim3(1, 4, 256), 256, FLASH_SMEM>>>(
        qkvh, qkvl, 3072,
        qkvh + 1024, qkvl + 1024, 3072,
        qkvh + 2048, qkvl + 2048, 3072,
        ctx, T_LEN);
    gemm_tf32<<<dim3(8, 64), 256, SMG>>>(
        ctx, 1024, w + WS_SA_OUT, 1024,
        sa_out_b, x, out, nullptr, nullptr, 1024, 1024, 0);

    // ================= cross attention =================
    ln_kernel<<<MQ, 256>>>(out, ln2_g, ln2_b, h);
    gemm_tf32<<<dim3(8, 64), 256, SMG>>>(
        h, 1024, w + WS_CA_IN, 1024,
        ca_in_b, nullptr, nullptr, qkvh, qkvl, 1024, 1024, 0);
    gemm_tf32<<<dim3(16, 128), 256, SMG>>>(
        hidc, 1024, w + WS_CA_IN + 1048576, 1024,
        ca_in_b + 1024, nullptr, nullptr, kvh, kvl, 2048, 1024, 0);
    flash_kernel<<<dim3(1, 4, 256), 256, FLASH_SMEM>>>(
        qkvh, qkvl, 1024,
        kvh, kvl, 2048,
        kvh + 1024, kvl + 1024, 2048,
        ctx, S_LEN);
    gemm_tf32<<<dim3(8, 64), 256, SMG>>>(
        ctx, 1024, w + WS_CA_OUT, 1024,
        ca_out_b, out, out, nullptr, nullptr, 1024, 1024, 0);

    // ================= MLP =================
    ln_kernel<<<MQ, 256>>>(out, ln3_g, ln3_b, h);
    gemm_tf32<<<dim3(32, 64), 256, SMG>>>(
        h, 1024, w + WS_FC, 1024,
        fc_b, nullptr, ffn, nullptr, nullptr, 4096, 1024, 1);
    gemm_tf32<<<dim3(8, 64), 256, SMG>>>(
        ffn, 4096, w + WS_PROJ, 4096,
        proj_b, out, out, nullptr, nullptr, 1024, 4096, 0);
}

// round 8
// speedup vs baseline: 6.4954x; 1.0186x over previous
#include <cuda_runtime.h>
#include <cuda_bf16.h>
#include <math.h>
#include <stdint.h>

#define D_MODEL 1024
#define N_HEAD  16
#define T_LEN   512
#define S_LEN   1024
#define BATCH   16
#define MQ      (T_LEN * BATCH)   /* 8192  query rows  */
#define MKV     (S_LEN * BATCH)   /* 16384 kv rows     */
typedef __nv_bfloat16 bf16;

// ---------------- scratch (static device globals; no allocation) ------------
#define WS_SA_IN  0u
#define WS_SA_OUT (3u*1024*1024)
#define WS_CA_IN  (4u*1024*1024)
#define WS_CA_OUT (7u*1024*1024)
#define WS_FC     (8u*1024*1024)
#define WS_PROJ   (12u*1024*1024)
#define WS_TOTAL  (16u*1024*1024)
__device__ float g_w  [WS_TOTAL];             // tf32-rounded weights
__device__ float g_hid[MKV * D_MODEL];        // tf32-rounded hidden_states
__device__ float g_h  [MQ * D_MODEL];         // LN output (tf32-rounded)
__device__ bf16  g_qkv_hi[MQ*3*D_MODEL],  g_qkv_lo[MQ*3*D_MODEL];
__device__ bf16  g_kv_hi[MKV*2*D_MODEL],  g_kv_lo[MKV*2*D_MODEL];
__device__ float g_ctx[MQ * D_MODEL];         // flash output (tf32-rounded)
__device__ float g_ffn[MQ * 4 * D_MODEL];     // MLP hidden (tf32-rounded)

__device__ __forceinline__ uint32_t b2u(__nv_bfloat162 x) {
    return *reinterpret_cast<uint32_t*>(&x);
}
__device__ __forceinline__ float rna(float x) {
    uint32_t u;
    asm("cvt.rna.tf32.f32 %0, %1;" : "=r"(u) : "f"(x));
    return __uint_as_float(u);
}
__device__ __forceinline__ uint32_t smem_u32(const void* p) {
    uint32_t a;
    asm("{ .reg .u64 t; cvta.to.shared.u64 t, %1; cvt.u32.u64 %0, t; }"
        : "=r"(a) : "l"(p));
    return a;
}
__device__ __forceinline__ void cp_async16(uint32_t s, const void* g) {
    asm volatile("cp.async.cg.shared.global [%0], [%1], 16;" :: "r"(s), "l"(g));
}
__device__ __forceinline__ void cp_commit() {
    asm volatile("cp.async.commit_group;");
}
__device__ __forceinline__ void cp_wait1() {
    asm volatile("cp.async.wait_group 1;");
}
__device__ __forceinline__ void ldsm4(uint32_t* r, uint32_t addr) {
    asm volatile("ldmatrix.sync.aligned.m8n8.x4.shared.b16 {%0,%1,%2,%3}, [%4];"
                 : "=r"(r[0]), "=r"(r[1]), "=r"(r[2]), "=r"(r[3]) : "r"(addr));
}
__device__ __forceinline__ void ldsm4t(uint32_t* r, uint32_t addr) {
    asm volatile("ldmatrix.sync.aligned.m8n8.x4.trans.shared.b16 {%0,%1,%2,%3}, [%4];"
                 : "=r"(r[0]), "=r"(r[1]), "=r"(r[2]), "=r"(r[3]) : "r"(addr));
}
__device__ __forceinline__ void mma_bf16(float* c, const uint32_t* a,
                                         const uint32_t* b) {
    asm volatile(
        "mma.sync.aligned.m16n8k16.row.col.f32.bf16.bf16.f32 "
        "{%0,%1,%2,%3}, {%4,%5,%6,%7}, {%8,%9}, {%0,%1,%2,%3};"
        : "+f"(c[0]), "+f"(c[1]), "+f"(c[2]), "+f"(c[3])
        : "r"(a[0]), "r"(a[1]), "r"(a[2]), "r"(a[3]),
          "r"(b[0]), "r"(b[1]));
}
__device__ __forceinline__ void mma_tf32(float* c, const uint32_t* a,
                                         const uint32_t* b) {
    asm volatile(
        "mma.sync.aligned.m16n8k8.row.col.f32.tf32.tf32.f32 "
        "{%0,%1,%2,%3}, {%4,%5,%6,%7}, {%8,%9}, {%0,%1,%2,%3};"
        : "+f"(c[0]), "+f"(c[1]), "+f"(c[2]), "+f"(c[3])
        : "r"(a[0]), "r"(a[1]), "r"(a[2]), "r"(a[3]),
          "r"(b[0]), "r"(b[1]));
}
__device__ __forceinline__ void pack2(float x, float y,
                                      uint32_t& hi, uint32_t& lo) {
    __nv_bfloat162 h = __floats2bfloat162_rn(x, y);
    float2 f = __bfloat1622float2(h);
    __nv_bfloat162 l = __floats2bfloat162_rn(x - f.x, y - f.y);
    hi = b2u(h); lo = b2u(l);
}

// ======================= TF32 single-pass GEMM ==============================
__global__ __launch_bounds__(256, 2) void gemm_tf32(
    const float* __restrict__ A, int lda,
    const float* __restrict__ B, int ldb,
    const float* __restrict__ bias,
    const float* __restrict__ res,
    float* __restrict__ Cf, bf16* __restrict__ Chi, bf16* __restrict__ Clo,
    int ldc, int K, int act)
{
    extern __shared__ char dsm[];
    const uint32_t smem_base = smem_u32(dsm);
    const int tid = threadIdx.x, wid = tid >> 5, lane = tid & 31;
    const int wm = wid >> 1, wn = wid & 1;
    const int m0 = blockIdx.y * 128, n0 = blockIdx.x * 128;

    float acc[2][8][4];
    #pragma unroll
    for (int i = 0; i < 2; i++)
        #pragma unroll
        for (int j = 0; j < 8; j++)
            #pragma unroll
            for (int q = 0; q < 4; q++) acc[i][j][q] = 0.f;

    const int nCh = K >> 5;
    auto issue = [&](int c, int s) {
        const int k0 = c << 5;
        const uint32_t sb = smem_base + s * 32768;
        #pragma unroll
        for (int it = 0; it < 4; it++) {
            int idx = tid + (it << 8);
            int r = idx >> 3, q = idx & 7;
            uint32_t so = sb + r * 128 + ((q ^ (r & 7)) << 4);
            cp_async16(so, A + (size_t)(m0 + r) * lda + k0 + q * 4);
        }
        #pragma unroll
        for (int it = 0; it < 4; it++) {
            int idx = tid + (it << 8);
            int r = idx >> 3, q = idx & 7;
            uint32_t so = sb + 16384 + r * 128 + ((q ^ (r & 7)) << 4);
            cp_async16(so, B + (size_t)(n0 + r) * ldb + k0 + q * 4);
        }
    };

    issue(0, 0); cp_commit();
    issue(1, 1); cp_commit();

    for (int c = 0; c < nCh; c++) {
        const int s = c & 1;
        cp_wait1();
        __syncthreads();
        const uint32_t sb = smem_base + s * 32768;
        #pragma unroll
        for (int ks = 0; ks < 4; ks++) {
            uint32_t a[2][4];
            #pragma unroll
            for (int mt = 0; mt < 2; mt++) {
                int row = wm * 32 + mt * 16 + (lane & 15);
                int q   = 2 * ks + (lane >> 4);
                ldsm4(a[mt], sb + row * 128 + ((q ^ (row & 7)) << 4));
            }
            #pragma unroll
            for (int ntp = 0; ntp < 4; ntp++) {
                int nrow = wn * 64 + ntp * 16 + (lane & 7)
                         + ((lane & 16) ? 8 : 0);
                int q    = 2 * ks + ((lane >> 3) & 1);
                uint32_t b[4];
                ldsm4(b, sb + 16384 + nrow * 128 + ((q ^ (nrow & 7)) << 4));
                #pragma unroll
                for (int half = 0; half < 2; half++) {
                    int nt = ntp * 2 + half;
                    mma_tf32(acc[0][nt], a[0], b + half * 2);
                    mma_tf32(acc[1][nt], a[1], b + half * 2);
                }
            }
        }
        __syncthreads();
        if (c + 2 < nCh) issue(c + 2, s);
        cp_commit();
    }

    const int r0 = m0 + wm * 32 + (lane >> 2);
    const int c0 = n0 + wn * 64 + (lane & 3) * 2;
    #pragma unroll
    for (int mt = 0; mt < 2; mt++) {
        #pragma unroll
        for (int nt = 0; nt < 8; nt++) {
            int col = c0 + nt * 8;
            float2 bv = make_float2(0.f, 0.f);
            if (bias) bv = *(const float2*)(bias + col);
            #pragma unroll
            for (int hrow = 0; hrow < 2; hrow++) {
                int row = r0 + mt * 16 + hrow * 8;
                float2 vv;
                vv.x = acc[mt][nt][hrow * 2 + 0] + bv.x;
                vv.y = acc[mt][nt][hrow * 2 + 1] + bv.y;
                size_t co = (size_t)row * ldc + col;
                if (res) {
                    float2 rr = *(const float2*)(res + co);
                    vv.x += rr.x; vv.y += rr.y;
                }
                if (act) {
                    vv.x = rna(vv.x / (1.f + __expf(-1.702f * vv.x)));
                    vv.y = rna(vv.y / (1.f + __expf(-1.702f * vv.y)));
                }
                if (Cf) {
                    *(float2*)(Cf + co) = vv;
                } else {
                    uint32_t ph, pll;
                    pack2(vv.x, vv.y, ph, pll);
                    *(uint32_t*)(Chi + co) = ph;
                    *(uint32_t*)(Clo + co) = pll;
                }
            }
        }
    }
}

// ======================= flash attention (bf16 3-pass) ======================
#define FLASH_SMEM (32768 + 2 * 32768)
__global__ __launch_bounds__(256) void flash_kernel(
    const bf16* __restrict__ Qh, const bf16* __restrict__ Ql, int ldq,
    const bf16* __restrict__ Kh, const bf16* __restrict__ Kl, int ldk,
    const bf16* __restrict__ Vh, const bf16* __restrict__ Vl, int ldv,
    float* __restrict__ O, int S)
{
    extern __shared__ char dsm[];
    const uint32_t sQ  = smem_u32(dsm);
    const uint32_t sKV = sQ + 32768;
    const int tid = threadIdx.x, wid = tid >> 5, lane = tid & 31;
    const int z = blockIdx.z, b = z & 15, h = z >> 4;
    const int t0 = blockIdx.y * 128;
    const int hcol = h * 64;

    #pragma unroll
    for (int p = 0; p < 4; p++) {
        int idx = tid + (p << 8);
        int r = idx >> 3, q = idx & 7;
        uint32_t so = sQ + r * 128 + ((q ^ (r & 7)) << 4);
        size_t g = (size_t)((t0 + r) * BATCH + b) * ldq + hcol + q * 8;
        cp_async16(so,         Qh + g);
        cp_async16(so + 16384, Ql + g);
    }
    auto issue_kv = [&](int c, int st) {
        int s0 = c << 6;
        uint32_t sb = sKV + st * 32768;
        #pragma unroll
        for (int p = 0; p < 2; p++) {
            int idx = tid + (p << 8);
            int r = idx >> 3, q = idx & 7;
            uint32_t so = sb + r * 128 + ((q ^ (r & 7)) << 4);
            size_t rowg = (size_t)((s0 + r) * BATCH + b);
            size_t gk = rowg * ldk + hcol + q * 8;
            size_t gv = rowg * ldv + hcol + q * 8;
            cp_async16(so,         Kh + gk);
            cp_async16(so + 8192,  Kl + gk);
            cp_async16(so + 16384, Vh + gv);
            cp_async16(so + 24576, Vl + gv);
        }
    };
    issue_kv(0, 0); cp_commit();
    issue_kv(1, 1); cp_commit();

    float out[8][4];
    #pragma unroll
    for (int i = 0; i < 8; i++)
        #pragma unroll
        for (int j = 0; j < 4; j++) out[i][j] = 0.f;
    float mrow0 = -1e30f, mrow1 = -1e30f, lrow0 = 0.f, lrow1 = 0.f;

    const int nCh = S >> 6;
    for (int c = 0; c < nCh; c++) {
        cp_wait1();
        __syncthreads();
        const uint32_t sb = sKV + (c & 1) * 32768;

        float sc[8][4];
        #pragma unroll
        for (int i = 0; i < 8; i++)
            #pragma unroll
            for (int j = 0; j < 4; j++) sc[i][j] = 0.f;
        #pragma unroll
        for (int ks = 0; ks < 4; ks++) {
            uint32_t aH[4], aL[4];
            {
                int row = wid * 16 + (lane & 15);
                int cc  = 2 * ks + (lane >> 4);
                uint32_t off = row * 128 + ((cc ^ (row & 7)) << 4);
                ldsm4(aH, sQ + off);
                ldsm4(aL, sQ + 16384 + off);
            }
            #pragma unroll
            for (int ntp = 0; ntp < 4; ntp++) {
                int nrow = ntp * 16 + (lane & 7) + ((lane & 16) ? 8 : 0);
                int cc   = 2 * ks + ((lane >> 3) & 1);
                uint32_t off = nrow * 128 + ((cc ^ (nrow & 7)) << 4);
                uint32_t bH[4], bL[4];
                ldsm4(bH, sb + off);
                ldsm4(bL, sb + 8192 + off);
                #pragma unroll
                for (int half = 0; half < 2; half++) {
                    int nt = ntp * 2 + half;
                    mma_bf16(sc[nt], aH, bH + half * 2);
                    mma_bf16(sc[nt], aH, bL + half * 2);
                    mma_bf16(sc[nt], aL, bH + half * 2);
                }
            }
        }

        float mx0 = -1e30f, mx1 = -1e30f;
        #pragma unroll
        for (int nt = 0; nt < 8; nt++) {
            sc[nt][0] *= 0.125f; sc[nt][1] *= 0.125f;
            sc[nt][2] *= 0.125f; sc[nt][3] *= 0.125f;
            mx0 = fmaxf(mx0, fmaxf(sc[nt][0], sc[nt][1]));
            mx1 = fmaxf(mx1, fmaxf(sc[nt][2], sc[nt][3]));
        }
        mx0 = fmaxf(mx0, __shfl_xor_sync(~0u, mx0, 1));
        mx0 = fmaxf(mx0, __shfl_xor_sync(~0u, mx0, 2));
        mx1 = fmaxf(mx1, __shfl_xor_sync(~0u, mx1, 1));
        mx1 = fmaxf(mx1, __shfl_xor_sync(~0u, mx1, 2));
        float mn0 = fmaxf(mrow0, mx0), mn1 = fmaxf(mrow1, mx1);
        float cf0 = __expf(mrow0 - mn0), cf1 = __expf(mrow1 - mn1);
        mrow0 = mn0; mrow1 = mn1;
        float sum0 = 0.f, sum1 = 0.f;
        #pragma unroll
        for (int nt = 0; nt < 8; nt++) {
            sc[nt][0] = __expf(sc[nt][0] - mn0); sum0 += sc[nt][0];
            sc[nt][1] = __expf(sc[nt][1] - mn0); sum0 += sc[nt][1];
            sc[nt][2] = __expf(sc[nt][2] - mn1); sum1 += sc[nt][2];
            sc[nt][3] = __expf(sc[nt][3] - mn1); sum1 += sc[nt][3];
        }
        sum0 += __shfl_xor_sync(~0u, sum0, 1);
        sum0 += __shfl_xor_sync(~0u, sum0, 2);
        sum1 += __shfl_xor_sync(~0u, sum1, 1);
        sum1 += __shfl_xor_sync(~0u, sum1, 2);
        lrow0 = lrow0 * cf0 + sum0;
        lrow1 = lrow1 * cf1 + sum1;
        #pragma unroll
        for (int nt = 0; nt < 8; nt++) {
            out[nt][0] *= cf0; out[nt][1] *= cf0;
            out[nt][2] *= cf1; out[nt][3] *= cf1;
        }

        #pragma unroll
        for (int t = 0; t < 4; t++) {
            uint32_t aPh[4], aPl[4];
            pack2(sc[2*t][0],   sc[2*t][1],   aPh[0], aPl[0]);
            pack2(sc[2*t][2],   sc[2*t][3],   aPh[1], aPl[1]);
            pack2(sc[2*t+1][0], sc[2*t+1][1], aPh[2], aPl[2]);
            pack2(sc[2*t+1][2], sc[2*t+1][3], aPh[3], aPl[3]);
            #pragma unroll
            for (int ntp = 0; ntp < 4; ntp++) {
                int row = 16 * t + (lane & 7) + ((lane & 8) ? 8 : 0);
                int cc  = 2 * ntp + (lane >> 4);
                uint32_t off = row * 128 + ((cc ^ (row & 7)) << 4);
                uint32_t bH[4], bL[4];
                ldsm4t(bH, sb + 16384 + off);
                ldsm4t(bL, sb + 24576 + off);
                #pragma unroll
                for (int half = 0; half < 2; half++) {
                    int nt = ntp * 2 + half;
                    mma_bf16(out[nt], aPh, bH + half * 2);
                    mma_bf16(out[nt], aPh, bL + half * 2);
                    mma_bf16(out[nt], aPl, bH + half * 2);
                }
            }
        }
        __syncthreads();
        if (c + 2 < nCh) issue_kv(c + 2, c & 1);
        cp_commit();
    }

    float inv0 = 1.f / lrow0, inv1 = 1.f / lrow1;
    int trow0 = t0 + wid * 16 + (lane >> 2);
    size_t gr0 = (size_t)(trow0 * BATCH + b) * D_MODEL;
    size_t gr1 = (size_t)((trow0 + 8) * BATCH + b) * D_MODEL;
    #pragma unroll
    for (int nt = 0; nt < 8; nt++) {
        int col = hcol + nt * 8 + (lane & 3) * 2;
        *(float2*)(O + gr0 + col) =
            make_float2(rna(out[nt][0] * inv0), rna(out[nt][1] * inv0));
        *(float2*)(O + gr1 + col) =
            make_float2(rna(out[nt][2] * inv1), rna(out[nt][3] * inv1));
    }
}

// ---------------- RNA tf32-round convert -------------------------------------
__global__ __launch_bounds__(256) void cvt_kernel(
    const float4* __restrict__ src, float4* __restrict__ dst)
{
    size_t i = (size_t)blockIdx.x * 256 + threadIdx.x;
    float4 v = src[i];
    dst[i] = make_float4(rna(v.x), rna(v.y), rna(v.z), rna(v.w));
}

// ---------------- LayerNorm -> RNA tf32 fp32 ---------------------------------
__global__ __launch_bounds__(256) void ln_kernel(
    const float* __restrict__ x, const float* __restrict__ g,
    const float* __restrict__ b, float* __restrict__ y)
{
    int row = blockIdx.x;
    const float4* xr = (const float4*)(x + (size_t)row * D_MODEL);
    int tid = threadIdx.x;
    float4 v = xr[tid];
    float s  = v.x + v.y + v.z + v.w;
    float ss = v.x*v.x + v.y*v.y + v.z*v.z + v.w*v.w;
    #pragma unroll
    for (int o = 16; o; o >>= 1) {
        s  += __shfl_xor_sync(~0u, s,  o);
        ss += __shfl_xor_sync(~0u, ss, o);
    }
    __shared__ float smS[8], smSS[8];
    int w = tid >> 5;
    if ((tid & 31) == 0) { smS[w] = s; smSS[w] = ss; }
    __syncthreads();
    if (tid < 32) {
        s  = (tid < 8) ? smS[tid]  : 0.f;
        ss = (tid < 8) ? smSS[tid] : 0.f;
        #pragma unroll
        for (int o = 4; o; o >>= 1) {
            s  += __shfl_xor_sync(~0u, s,  o);
            ss += __shfl_xor_sync(~0u, ss, o);
        }
        if (tid == 0) { smS[0] = s; smSS[0] = ss; }
    }
    __syncthreads();
    float mean = smS[0] * (1.f / D_MODEL);
    float var  = smSS[0] * (1.f / D_MODEL) - mean * mean;
    float rstd = rsqrtf(var + 1e-5f);
    float4 gv = ((const float4*)g)[tid];
    float4 bv = ((const float4*)b)[tid];
    float4 o;
    o.x = rna((v.x - mean) * rstd * gv.x + bv.x);
    o.y = rna((v.y - mean) * rstd * gv.y + bv.y);
    o.z = rna((v.z - mean) * rstd * gv.z + bv.z);
    o.w = rna((v.w - mean) * rstd * gv.w + bv.w);
    ((float4*)(y + (size_t)row * D_MODEL))[tid] = o;
}

// ---------------- orchestration ---------------------------------------------
extern "C" void kernel_launch(void* const* d_in, const int* in_sizes, int n_in,
                              void* d_out, int out_size)
{
    const float* x        = (const float*)d_in[0];
    const float* hid      = (const float*)d_in[1];
    const float* ln1_g    = (const float*)d_in[2];
    const float* ln1_b    = (const float*)d_in[3];
    const float* sa_in_w  = (const float*)d_in[4];
    const float* sa_in_b  = (const float*)d_in[5];
    const float* sa_out_w = (const float*)d_in[6];
    const float* sa_out_b = (const float*)d_in[7];
    const float* ln2_g    = (const float*)d_in[8];
    const float* ln2_b    = (const float*)d_in[9];
    const float* ca_in_w  = (const float*)d_in[10];
    const float* ca_in_b  = (const float*)d_in[11];
    const float* ca_out_w = (const float*)d_in[12];
    const float* ca_out_b = (const float*)d_in[13];
    const float* ln3_g    = (const float*)d_in[14];
    const float* ln3_b    = (const float*)d_in[15];
    const float* fc_w     = (const float*)d_in[16];
    const float* fc_b     = (const float*)d_in[17];
    const float* proj_w   = (const float*)d_in[18];
    const float* proj_b   = (const float*)d_in[19];
    float* out = (float*)d_out;

    float *w, *hidc, *h, *ctx, *ffn;
    bf16 *qkvh, *qkvl, *kvh, *kvl;
    cudaGetSymbolAddress((void**)&w,    g_w);
    cudaGetSymbolAddress((void**)&hidc, g_hid);
    cudaGetSymbolAddress((void**)&h,    g_h);
    cudaGetSymbolAddress((void**)&qkvh, g_qkv_hi);
    cudaGetSymbolAddress((void**)&qkvl, g_qkv_lo);
    cudaGetSymbolAddress((void**)&kvh,  g_kv_hi);
    cudaGetSymbolAddress((void**)&kvl,  g_kv_lo);
    cudaGetSymbolAddress((void**)&ctx,  g_ctx);
    cudaGetSymbolAddress((void**)&ffn,  g_ffn);

    const int SMG = 65536;
    cudaFuncSetAttribute(gemm_tf32,
                         cudaFuncAttributeMaxDynamicSharedMemorySize, SMG);
    cudaFuncSetAttribute(flash_kernel,
                         cudaFuncAttributeMaxDynamicSharedMemorySize, FLASH_SMEM);

    // ---- side stream + events (created per call; harness only calls this
    //      a handful of times — correctness + capture — then replays graph) ----
    cudaStream_t sb;
    cudaStreamCreateWithFlags(&sb, cudaStreamNonBlocking);
    cudaEvent_t e0, eSAIN, eSAOUT, eCAIN, eKV, eCAOUT, eFC, ePROJ;
    cudaEventCreateWithFlags(&e0,     cudaEventDisableTiming);
    cudaEventCreateWithFlags(&eSAIN,  cudaEventDisableTiming);
    cudaEventCreateWithFlags(&eSAOUT, cudaEventDisableTiming);
    cudaEventCreateWithFlags(&eCAIN,  cudaEventDisableTiming);
    cudaEventCreateWithFlags(&eKV,    cudaEventDisableTiming);
    cudaEventCreateWithFlags(&eCAOUT, cudaEventDisableTiming);
    cudaEventCreateWithFlags(&eFC,    cudaEventDisableTiming);
    cudaEventCreateWithFlags(&ePROJ,  cudaEventDisableTiming);

    // fork side stream from main
    cudaEventRecord(e0, 0);
    cudaStreamWaitEvent(sb, e0, 0);

    // ---- side stream: weight cvts + cross-KV GEMM ----
    cvt_kernel<<<3072, 256, 0, sb>>>((const float4*)sa_in_w,
                                     (float4*)(w + WS_SA_IN));
    cudaEventRecord(eSAIN, sb);
    cvt_kernel<<<1024, 256, 0, sb>>>((const float4*)sa_out_w,
                                     (float4*)(w + WS_SA_OUT));
    cudaEventRecord(eSAOUT, sb);
    cvt_kernel<<<3072, 256, 0, sb>>>((const float4*)ca_in_w,
                                     (float4*)(w + WS_CA_IN));
    cudaEventRecord(eCAIN, sb);
    cvt_kernel<<<16384, 256, 0, sb>>>((const float4*)hid, (float4*)hidc);
    gemm_tf32<<<dim3(16, 128), 256, SMG, sb>>>(
        hidc, 1024, w + WS_CA_IN + 1048576, 1024,
        ca_in_b + 1024, nullptr, nullptr, kvh, kvl, 2048, 1024, 0);
    cudaEventRecord(eKV, sb);
    cvt_kernel<<<1024, 256, 0, sb>>>((const float4*)ca_out_w,
                                     (float4*)(w + WS_CA_OUT));
    cudaEventRecord(eCAOUT, sb);
    cvt_kernel<<<4096, 256, 0, sb>>>((const float4*)fc_w,
                                     (float4*)(w + WS_FC));
    cudaEventRecord(eFC, sb);
    cvt_kernel<<<4096, 256, 0, sb>>>((const float4*)proj_w,
                                     (float4*)(w + WS_PROJ));
    cudaEventRecord(ePROJ, sb);

    // ---- main stream: self attention ----
    ln_kernel<<<MQ, 256>>>(x, ln1_g, ln1_b, h);
    cudaStreamWaitEvent(0, eSAIN, 0);
    gemm_tf32<<<dim3(24, 64), 256, SMG>>>(
        h, 1024, w + WS_SA_IN, 1024,
        sa_in_b, nullptr, nullptr, qkvh, qkvl, 3072, 1024, 0);
    flash_kernel<<<dim3(1, 4, 256), 256, FLASH_SMEM>>>(
        qkvh, qkvl, 3072,
        qkvh + 1024, qkvl + 1024, 3072,
        qkvh + 2048, qkvl + 2048, 3072,
        ctx, T_LEN);
    cudaStreamWaitEvent(0, eSAOUT, 0);
    gemm_tf32<<<dim3(8, 64), 256, SMG>>>(
        ctx, 1024, w + WS_SA_OUT, 1024,
        sa_out_b, x, out, nullptr, nullptr, 1024, 1024, 0);

    // ---- main stream: cross attention ----
    ln_kernel<<<MQ, 256>>>(out, ln2_g, ln2_b, h);
    cudaStreamWaitEvent(0, eCAIN, 0);
    gemm_tf32<<<dim3(8, 64), 256, SMG>>>(
        h, 1024, w + WS_CA_IN, 1024,
        ca_in_b, nullptr, nullptr, qkvh, qkvl, 1024, 1024, 0);
    cudaStreamWaitEvent(0, eKV, 0);
    flash_kernel<<<dim3(1, 4, 256), 256, FLASH_SMEM>>>(
        qkvh, qkvl, 1024,
        kvh, kvl, 2048,
        kvh + 1024, kvl + 1024, 2048,
        ctx, S_LEN);
    cudaStreamWaitEvent(0, eCAOUT, 0);
    gemm_tf32<<<dim3(8, 64), 256, SMG>>>(
        ctx, 1024, w + WS_CA_OUT, 1024,
        ca_out_b, out, out, nullptr, nullptr, 1024, 1024, 0);

    // ---- main stream: MLP ----
    ln_kernel<<<MQ, 256>>>(out, ln3_g, ln3_b, h);
    cudaStreamWaitEvent(0, eFC, 0);
    gemm_tf32<<<dim3(32, 64), 256, SMG>>>(
        h, 1024, w + WS_FC, 1024,
        fc_b, nullptr, ffn, nullptr, nullptr, 4096, 1024, 1);
    cudaStreamWaitEvent(0, ePROJ, 0);
    gemm_tf32<<<dim3(8, 64), 256, SMG>>>(
        ffn, 4096, w + WS_PROJ, 4096,
        proj_b, out, out, nullptr, nullptr, 1024, 4096, 0);
}

// round 9
// speedup vs baseline: 11.4518x; 1.7631x over previous
#include <cuda_runtime.h>
#include <cuda_fp16.h>
#include <math.h>
#include <stdint.h>

#define D_MODEL 1024
#define N_HEAD  16
#define T_LEN   512
#define S_LEN   1024
#define BATCH   16
#define MQ      (T_LEN * BATCH)   /* 8192  query rows  */
#define MKV     (S_LEN * BATCH)   /* 16384 kv rows     */

// ---------------- scratch (static device globals; no allocation) ------------
#define WS_SA_IN  0u
#define WS_SA_OUT (3u*1024*1024)
#define WS_CA_IN  (4u*1024*1024)
#define WS_CA_OUT (7u*1024*1024)
#define WS_FC     (8u*1024*1024)
#define WS_PROJ   (12u*1024*1024)
#define WS_TOTAL  (16u*1024*1024)
__device__ __half g_w  [WS_TOTAL];            // fp16 weights
__device__ __half g_hid[MKV * D_MODEL];       // fp16 hidden_states
__device__ __half g_h  [MQ * D_MODEL];        // LN output
__device__ __half g_qkv[MQ * 3 * D_MODEL];
__device__ __half g_kv [MKV * 2 * D_MODEL];
__device__ __half g_ctx[MQ * D_MODEL];
__device__ __half g_ffn[MQ * 4 * D_MODEL];

__device__ __forceinline__ uint32_t h2u(__half2 x) {
    return *reinterpret_cast<uint32_t*>(&x);
}
__device__ __forceinline__ uint32_t smem_u32(const void* p) {
    uint32_t a;
    asm("{ .reg .u64 t; cvta.to.shared.u64 t, %1; cvt.u32.u64 %0, t; }"
        : "=r"(a) : "l"(p));
    return a;
}
__device__ __forceinline__ void cp_async16(uint32_t s, const void* g) {
    asm volatile("cp.async.cg.shared.global [%0], [%1], 16;" :: "r"(s), "l"(g));
}
__device__ __forceinline__ void cp_commit() {
    asm volatile("cp.async.commit_group;");
}
__device__ __forceinline__ void cp_wait1() {
    asm volatile("cp.async.wait_group 1;");
}
__device__ __forceinline__ void ldsm4(uint32_t* r, uint32_t addr) {
    asm volatile("ldmatrix.sync.aligned.m8n8.x4.shared.b16 {%0,%1,%2,%3}, [%4];"
                 : "=r"(r[0]), "=r"(r[1]), "=r"(r[2]), "=r"(r[3]) : "r"(addr));
}
__device__ __forceinline__ void ldsm4t(uint32_t* r, uint32_t addr) {
    asm volatile("ldmatrix.sync.aligned.m8n8.x4.trans.shared.b16 {%0,%1,%2,%3}, [%4];"
                 : "=r"(r[0]), "=r"(r[1]), "=r"(r[2]), "=r"(r[3]) : "r"(addr));
}
__device__ __forceinline__ void mma_fp16(float* c, const uint32_t* a,
                                         const uint32_t* b) {
    asm volatile(
        "mma.sync.aligned.m16n8k16.row.col.f32.f16.f16.f32 "
        "{%0,%1,%2,%3}, {%4,%5,%6,%7}, {%8,%9}, {%0,%1,%2,%3};"
        : "+f"(c[0]), "+f"(c[1]), "+f"(c[2]), "+f"(c[3])
        : "r"(a[0]), "r"(a[1]), "r"(a[2]), "r"(a[3]),
          "r"(b[0]), "r"(b[1]));
}

// ======================= FP16 single-pass GEMM ==============================
// C[m,n] = sum_k A[m,k]*B[n,k]; fp16 operands, fp32 accumulate.
// Tile 128x128, BK=32 (64B rows, 16B-chunk XOR swizzle), 2-stage cp.async.
// 8 warps 4x2. Output fp32 (Cf, +bias +res +act) or fp16 (Ch).
__global__ __launch_bounds__(256, 2) void gemm_fp16(
    const __half* __restrict__ A, int lda,
    const __half* __restrict__ B, int ldb,
    const float* __restrict__ bias,
    const float* __restrict__ res,
    float* __restrict__ Cf, __half* __restrict__ Ch,
    int ldc, int K, int act)
{
    extern __shared__ char dsm[];
    const uint32_t smem_base = smem_u32(dsm);
    const int tid = threadIdx.x, wid = tid >> 5, lane = tid & 31;
    const int wm = wid >> 1, wn = wid & 1;
    const int m0 = blockIdx.y * 128, n0 = blockIdx.x * 128;

    float acc[2][8][4];
    #pragma unroll
    for (int i = 0; i < 2; i++)
        #pragma unroll
        for (int j = 0; j < 8; j++)
            #pragma unroll
            for (int q = 0; q < 4; q++) acc[i][j][q] = 0.f;

    const int nCh = K >> 5;
    auto issue = [&](int c, int s) {
        const int k0 = c << 5;
        const uint32_t sb = smem_base + s * 16384;
        #pragma unroll
        for (int it = 0; it < 2; it++) {
            int j = tid + (it << 8);
            int r = j >> 2, q = j & 3;
            uint32_t so = sb + r * 64 + ((q ^ ((r >> 1) & 3)) << 4);
            cp_async16(so, A + (size_t)(m0 + r) * lda + k0 + q * 8);
        }
        #pragma unroll
        for (int it = 0; it < 2; it++) {
            int j = tid + (it << 8);
            int n = j >> 2, q = j & 3;
            uint32_t so = sb + 8192 + n * 64 + ((q ^ ((n >> 1) & 3)) << 4);
            cp_async16(so, B + (size_t)(n0 + n) * ldb + k0 + q * 8);
        }
    };

    issue(0, 0); cp_commit();
    issue(1, 1); cp_commit();

    for (int c = 0; c < nCh; c++) {
        const int s = c & 1;
        cp_wait1();
        __syncthreads();
        const uint32_t sb = smem_base + s * 16384;
        #pragma unroll
        for (int ks = 0; ks < 2; ks++) {
            uint32_t a[2][4];
            #pragma unroll
            for (int mt = 0; mt < 2; mt++) {
                int row = wm * 32 + mt * 16 + (lane & 15);
                int cc  = 2 * ks + (lane >> 4);
                ldsm4(a[mt], sb + row * 64 + ((cc ^ ((row >> 1) & 3)) << 4));
            }
            #pragma unroll
            for (int ntp = 0; ntp < 4; ntp++) {
                int nrow = wn * 64 + ntp * 16 + (lane & 7)
                         + ((lane & 16) ? 8 : 0);
                int cc   = 2 * ks + ((lane >> 3) & 1);
                uint32_t b[4];
                ldsm4(b, sb + 8192 + nrow * 64
                         + ((cc ^ ((nrow >> 1) & 3)) << 4));
                #pragma unroll
                for (int half = 0; half < 2; half++) {
                    int nt = ntp * 2 + half;
                    mma_fp16(acc[0][nt], a[0], b + half * 2);
                    mma_fp16(acc[1][nt], a[1], b + half * 2);
                }
            }
        }
        __syncthreads();
        if (c + 2 < nCh) issue(c + 2, s);
        cp_commit();
    }

    const int r0 = m0 + wm * 32 + (lane >> 2);
    const int c0 = n0 + wn * 64 + (lane & 3) * 2;
    #pragma unroll
    for (int mt = 0; mt < 2; mt++) {
        #pragma unroll
        for (int nt = 0; nt < 8; nt++) {
            int col = c0 + nt * 8;
            float2 bv = make_float2(0.f, 0.f);
            if (bias) bv = *(const float2*)(bias + col);
            #pragma unroll
            for (int hrow = 0; hrow < 2; hrow++) {
                int row = r0 + mt * 16 + hrow * 8;
                float2 vv;
                vv.x = acc[mt][nt][hrow * 2 + 0] + bv.x;
                vv.y = acc[mt][nt][hrow * 2 + 1] + bv.y;
                size_t co = (size_t)row * ldc + col;
                if (res) {
                    float2 rr = *(const float2*)(res + co);
                    vv.x += rr.x; vv.y += rr.y;
                }
                if (act) {
                    vv.x = vv.x / (1.f + __expf(-1.702f * vv.x));
                    vv.y = vv.y / (1.f + __expf(-1.702f * vv.y));
                }
                if (Cf) {
                    *(float2*)(Cf + co) = vv;
                } else {
                    *(uint32_t*)(Ch + co) = h2u(__floats2half2_rn(vv.x, vv.y));
                }
            }
        }
    }
}

// ======================= flash attention (fp16 single-pass) =================
// Grid (1, T/128, 256). smem: Q 16KB + 2 stages x (K 8KB | V 8KB) = 48KB.
#define FLASH_SMEM (16384 + 2 * 16384)
__global__ __launch_bounds__(256) void flash_kernel(
    const __half* __restrict__ Q, int ldq,
    const __half* __restrict__ K, int ldk,
    const __half* __restrict__ V, int ldv,
    __half* __restrict__ O, int S)
{
    extern __shared__ char dsm[];
    const uint32_t sQ  = smem_u32(dsm);
    const uint32_t sKV = sQ + 16384;
    const int tid = threadIdx.x, wid = tid >> 5, lane = tid & 31;
    const int z = blockIdx.z, b = z & 15, h = z >> 4;
    const int t0 = blockIdx.y * 128;
    const int hcol = h * 64;

    #pragma unroll
    for (int p = 0; p < 4; p++) {
        int idx = tid + (p << 8);
        int r = idx >> 3, q = idx & 7;
        uint32_t so = sQ + r * 128 + ((q ^ (r & 7)) << 4);
        cp_async16(so, Q + (size_t)((t0 + r) * BATCH + b) * ldq + hcol + q * 8);
    }
    auto issue_kv = [&](int c, int st) {
        int s0 = c << 6;
        uint32_t sb = sKV + st * 16384;
        #pragma unroll
        for (int p = 0; p < 2; p++) {
            int idx = tid + (p << 8);
            int r = idx >> 3, q = idx & 7;
            uint32_t so = sb + r * 128 + ((q ^ (r & 7)) << 4);
            size_t rowg = (size_t)((s0 + r) * BATCH + b);
            cp_async16(so,        K + rowg * ldk + hcol + q * 8);
            cp_async16(so + 8192, V + rowg * ldv + hcol + q * 8);
        }
    };
    issue_kv(0, 0); cp_commit();
    issue_kv(1, 1); cp_commit();

    float out[8][4];
    #pragma unroll
    for (int i = 0; i < 8; i++)
        #pragma unroll
        for (int j = 0; j < 4; j++) out[i][j] = 0.f;
    float mrow0 = -1e30f, mrow1 = -1e30f, lrow0 = 0.f, lrow1 = 0.f;

    const int nCh = S >> 6;
    for (int c = 0; c < nCh; c++) {
        cp_wait1();
        __syncthreads();
        const uint32_t sb = sKV + (c & 1) * 16384;

        // ---- scores ----
        float sc[8][4];
        #pragma unroll
        for (int i = 0; i < 8; i++)
            #pragma unroll
            for (int j = 0; j < 4; j++) sc[i][j] = 0.f;
        #pragma unroll
        for (int ks = 0; ks < 4; ks++) {
            uint32_t a[4];
            {
                int row = wid * 16 + (lane & 15);
                int cc  = 2 * ks + (lane >> 4);
                ldsm4(a, sQ + row * 128 + ((cc ^ (row & 7)) << 4));
            }
            #pragma unroll
            for (int ntp = 0; ntp < 4; ntp++) {
                int nrow = ntp * 16 + (lane & 7) + ((lane & 16) ? 8 : 0);
                int cc   = 2 * ks + ((lane >> 3) & 1);
                uint32_t bq[4];
                ldsm4(bq, sb + nrow * 128 + ((cc ^ (nrow & 7)) << 4));
                mma_fp16(sc[ntp * 2 + 0], a, bq);
                mma_fp16(sc[ntp * 2 + 1], a, bq + 2);
            }
        }

        // ---- online softmax ----
        float mx0 = -1e30f, mx1 = -1e30f;
        #pragma unroll
        for (int nt = 0; nt < 8; nt++) {
            sc[nt][0] *= 0.125f; sc[nt][1] *= 0.125f;
            sc[nt][2] *= 0.125f; sc[nt][3] *= 0.125f;
            mx0 = fmaxf(mx0, fmaxf(sc[nt][0], sc[nt][1]));
            mx1 = fmaxf(mx1, fmaxf(sc[nt][2], sc[nt][3]));
        }
        mx0 = fmaxf(mx0, __shfl_xor_sync(~0u, mx0, 1));
        mx0 = fmaxf(mx0, __shfl_xor_sync(~0u, mx0, 2));
        mx1 = fmaxf(mx1, __shfl_xor_sync(~0u, mx1, 1));
        mx1 = fmaxf(mx1, __shfl_xor_sync(~0u, mx1, 2));
        float mn0 = fmaxf(mrow0, mx0), mn1 = fmaxf(mrow1, mx1);
        float cf0 = __expf(mrow0 - mn0), cf1 = __expf(mrow1 - mn1);
        mrow0 = mn0; mrow1 = mn1;
        float sum0 = 0.f, sum1 = 0.f;
        #pragma unroll
        for (int nt = 0; nt < 8; nt++) {
            sc[nt][0] = __expf(sc[nt][0] - mn0); sum0 += sc[nt][0];
            sc[nt][1] = __expf(sc[nt][1] - mn0); sum0 += sc[nt][1];
            sc[nt][2] = __expf(sc[nt][2] - mn1); sum1 += sc[nt][2];
            sc[nt][3] = __expf(sc[nt][3] - mn1); sum1 += sc[nt][3];
        }
        sum0 += __shfl_xor_sync(~0u, sum0, 1);
        sum0 += __shfl_xor_sync(~0u, sum0, 2);
        sum1 += __shfl_xor_sync(~0u, sum1, 1);
        sum1 += __shfl_xor_sync(~0u, sum1, 2);
        lrow0 = lrow0 * cf0 + sum0;
        lrow1 = lrow1 * cf1 + sum1;
        #pragma unroll
        for (int nt = 0; nt < 8; nt++) {
            out[nt][0] *= cf0; out[nt][1] *= cf0;
            out[nt][2] *= cf1; out[nt][3] *= cf1;
        }

        // ---- PV ----
        #pragma unroll
        for (int t = 0; t < 4; t++) {
            uint32_t aP[4];
            aP[0] = h2u(__floats2half2_rn(sc[2*t][0],   sc[2*t][1]));
            aP[1] = h2u(__floats2half2_rn(sc[2*t][2],   sc[2*t][3]));
            aP[2] = h2u(__floats2half2_rn(sc[2*t+1][0], sc[2*t+1][1]));
            aP[3] = h2u(__floats2half2_rn(sc[2*t+1][2], sc[2*t+1][3]));
            #pragma unroll
            for (int ntp = 0; ntp < 4; ntp++) {
                int row = 16 * t + (lane & 7) + ((lane & 8) ? 8 : 0);
                int cc  = 2 * ntp + (lane >> 4);
                uint32_t bv[4];
                ldsm4t(bv, sb + 8192 + row * 128 + ((cc ^ (row & 7)) << 4));
                mma_fp16(out[ntp * 2 + 0], aP, bv);
                mma_fp16(out[ntp * 2 + 1], aP, bv + 2);
            }
        }
        __syncthreads();
        if (c + 2 < nCh) issue_kv(c + 2, c & 1);
        cp_commit();
    }

    float inv0 = 1.f / lrow0, inv1 = 1.f / lrow1;
    int trow0 = t0 + wid * 16 + (lane >> 2);
    size_t gr0 = (size_t)(trow0 * BATCH + b) * D_MODEL;
    size_t gr1 = (size_t)((trow0 + 8) * BATCH + b) * D_MODEL;
    #pragma unroll
    for (int nt = 0; nt < 8; nt++) {
        int col = hcol + nt * 8 + (lane & 3) * 2;
        *(uint32_t*)(O + gr0 + col) =
            h2u(__floats2half2_rn(out[nt][0] * inv0, out[nt][1] * inv0));
        *(uint32_t*)(O + gr1 + col) =
            h2u(__floats2half2_rn(out[nt][2] * inv1, out[nt][3] * inv1));
    }
}

// ---------------- fp32 -> fp16 convert ---------------------------------------
__global__ __launch_bounds__(256) void cvt_kernel(
    const float4* __restrict__ src, uint2* __restrict__ dst)
{
    size_t i = (size_t)blockIdx.x * 256 + threadIdx.x;
    float4 v = src[i];
    dst[i] = make_uint2(h2u(__floats2half2_rn(v.x, v.y)),
                        h2u(__floats2half2_rn(v.z, v.w)));
}

// ---------------- LayerNorm -> fp16 ------------------------------------------
__global__ __launch_bounds__(256) void ln_kernel(
    const float* __restrict__ x, const float* __restrict__ g,
    const float* __restrict__ b, __half* __restrict__ y)
{
    int row = blockIdx.x;
    const float4* xr = (const float4*)(x + (size_t)row * D_MODEL);
    int tid = threadIdx.x;
    float4 v = xr[tid];
    float s  = v.x + v.y + v.z + v.w;
    float ss = v.x*v.x + v.y*v.y + v.z*v.z + v.w*v.w;
    #pragma unroll
    for (int o = 16; o; o >>= 1) {
        s  += __shfl_xor_sync(~0u, s,  o);
        ss += __shfl_xor_sync(~0u, ss, o);
    }
    __shared__ float smS[8], smSS[8];
    int w = tid >> 5;
    if ((tid & 31) == 0) { smS[w] = s; smSS[w] = ss; }
    __syncthreads();
    if (tid < 32) {
        s  = (tid < 8) ? smS[tid]  : 0.f;
        ss = (tid < 8) ? smSS[tid] : 0.f;
        #pragma unroll
        for (int o = 4; o; o >>= 1) {
            s  += __shfl_xor_sync(~0u, s,  o);
            ss += __shfl_xor_sync(~0u, ss, o);
        }
        if (tid == 0) { smS[0] = s; smSS[0] = ss; }
    }
    __syncthreads();
    float mean = smS[0] * (1.f / D_MODEL);
    float var  = smSS[0] * (1.f / D_MODEL) - mean * mean;
    float rstd = rsqrtf(var + 1e-5f);
    float4 gv = ((const float4*)g)[tid];
    float4 bv = ((const float4*)b)[tid];
    float4 o;
    o.x = (v.x - mean) * rstd * gv.x + bv.x;
    o.y = (v.y - mean) * rstd * gv.y + bv.y;
    o.z = (v.z - mean) * rstd * gv.z + bv.z;
    o.w = (v.w - mean) * rstd * gv.w + bv.w;
    ((uint2*)(y + (size_t)row * D_MODEL))[tid] =
        make_uint2(h2u(__floats2half2_rn(o.x, o.y)),
                   h2u(__floats2half2_rn(o.z, o.w)));
}

// ---------------- orchestration ---------------------------------------------
extern "C" void kernel_launch(void* const* d_in, const int* in_sizes, int n_in,
                              void* d_out, int out_size)
{
    const float* x        = (const float*)d_in[0];
    const float* hid      = (const float*)d_in[1];
    const float* ln1_g    = (const float*)d_in[2];
    const float* ln1_b    = (const float*)d_in[3];
    const float* sa_in_w  = (const float*)d_in[4];
    const float* sa_in_b  = (const float*)d_in[5];
    const float* sa_out_w = (const float*)d_in[6];
    const float* sa_out_b = (const float*)d_in[7];
    const float* ln2_g    = (const float*)d_in[8];
    const float* ln2_b    = (const float*)d_in[9];
    const float* ca_in_w  = (const float*)d_in[10];
    const float* ca_in_b  = (const float*)d_in[11];
    const float* ca_out_w = (const float*)d_in[12];
    const float* ca_out_b = (const float*)d_in[13];
    const float* ln3_g    = (const float*)d_in[14];
    const float* ln3_b    = (const float*)d_in[15];
    const float* fc_w     = (const float*)d_in[16];
    const float* fc_b     = (const float*)d_in[17];
    const float* proj_w   = (const float*)d_in[18];
    const float* proj_b   = (const float*)d_in[19];
    float* out = (float*)d_out;

    __half *w, *hidc, *h, *qkv, *kv, *ctx, *ffn;
    cudaGetSymbolAddress((void**)&w,    g_w);
    cudaGetSymbolAddress((void**)&hidc, g_hid);
    cudaGetSymbolAddress((void**)&h,    g_h);
    cudaGetSymbolAddress((void**)&qkv,  g_qkv);
    cudaGetSymbolAddress((void**)&kv,   g_kv);
    cudaGetSymbolAddress((void**)&ctx,  g_ctx);
    cudaGetSymbolAddress((void**)&ffn,  g_ffn);

    const int SMG = 32768;
    cudaFuncSetAttribute(gemm_fp16,
                         cudaFuncAttributeMaxDynamicSharedMemorySize, SMG);
    cudaFuncSetAttribute(flash_kernel,
                         cudaFuncAttributeMaxDynamicSharedMemorySize, FLASH_SMEM);

    // ---- side stream + events ----
    cudaStream_t sb;
    cudaStreamCreateWithFlags(&sb, cudaStreamNonBlocking);
    cudaEvent_t e0, eSAIN, eSAOUT, eCAIN, eKV, eCAOUT, eFC, ePROJ;
    cudaEventCreateWithFlags(&e0,     cudaEventDisableTiming);
    cudaEventCreateWithFlags(&eSAIN,  cudaEventDisableTiming);
    cudaEventCreateWithFlags(&eSAOUT, cudaEventDisableTiming);
    cudaEventCreateWithFlags(&eCAIN,  cudaEventDisableTiming);
    cudaEventCreateWithFlags(&eKV,    cudaEventDisableTiming);
    cudaEventCreateWithFlags(&eCAOUT, cudaEventDisableTiming);
    cudaEventCreateWithFlags(&eFC,    cudaEventDisableTiming);
    cudaEventCreateWithFlags(&ePROJ,  cudaEventDisableTiming);

    cudaEventRecord(e0, 0);
    cudaStreamWaitEvent(sb, e0, 0);

    // ---- side stream: weight cvts + cross-KV GEMM ----
    cvt_kernel<<<3072, 256, 0, sb>>>((const float4*)sa_in_w,
                                     (uint2*)(w + WS_SA_IN));
    cudaEventRecord(eSAIN, sb);
    cvt_kernel<<<1024, 256, 0, sb>>>((const float4*)sa_out_w,
                                     (uint2*)(w + WS_SA_OUT));
    cudaEventRecord(eSAOUT, sb);
    cvt_kernel<<<3072, 256, 0, sb>>>((const float4*)ca_in_w,
                                     (uint2*)(w + WS_CA_IN));
    cudaEventRecord(eCAIN, sb);
    cvt_kernel<<<16384, 256, 0, sb>>>((const float4*)hid, (uint2*)hidc);
    gemm_fp16<<<dim3(16, 128), 256, SMG, sb>>>(
        hidc, 1024, w + WS_CA_IN + 1048576, 1024,
        ca_in_b + 1024, nullptr, nullptr, kv, 2048, 1024, 0);
    cudaEventRecord(eKV, sb);
    cvt_kernel<<<1024, 256, 0, sb>>>((const float4*)ca_out_w,
                                     (uint2*)(w + WS_CA_OUT));
    cudaEventRecord(eCAOUT, sb);
    cvt_kernel<<<4096, 256, 0, sb>>>((const float4*)fc_w,
                                     (uint2*)(w + WS_FC));
    cudaEventRecord(eFC, sb);
    cvt_kernel<<<4096, 256, 0, sb>>>((const float4*)proj_w,
                                     (uint2*)(w + WS_PROJ));
    cudaEventRecord(ePROJ, sb);

    // ---- main stream: self attention ----
    ln_kernel<<<MQ, 256>>>(x, ln1_g, ln1_b, h);
    cudaStreamWaitEvent(0, eSAIN, 0);
    gemm_fp16<<<dim3(24, 64), 256, SMG>>>(
        h, 1024, w + WS_SA_IN, 1024,
        sa_in_b, nullptr, nullptr, qkv, 3072, 1024, 0);
    flash_kernel<<<dim3(1, 4, 256), 256, FLASH_SMEM>>>(
        qkv, 3072, qkv + 1024, 3072, qkv + 2048, 3072, ctx, T_LEN);
    cudaStreamWaitEvent(0, eSAOUT, 0);
    gemm_fp16<<<dim3(8, 64), 256, SMG>>>(
        ctx, 1024, w + WS_SA_OUT, 1024,
        sa_out_b, x, out, nullptr, 1024, 1024, 0);

    // ---- main stream: cross attention ----
    ln_kernel<<<MQ, 256>>>(out, ln2_g, ln2_b, h);
    cudaStreamWaitEvent(0, eCAIN, 0);
    gemm_fp16<<<dim3(8, 64), 256, SMG>>>(
        h, 1024, w + WS_CA_IN, 1024,
        ca_in_b, nullptr, nullptr, qkv, 1024, 1024, 0);
    cudaStreamWaitEvent(0, eKV, 0);
    flash_kernel<<<dim3(1, 4, 256), 256, FLASH_SMEM>>>(
        qkv, 1024, kv, 2048, kv + 1024, 2048, ctx, S_LEN);
    cudaStreamWaitEvent(0, eCAOUT, 0);
    gemm_fp16<<<dim3(8, 64), 256, SMG>>>(
        ctx, 1024, w + WS_CA_OUT, 1024,
        ca_out_b, out, out, nullptr, 1024, 1024, 0);

    // ---- main stream: MLP ----
    ln_kernel<<<MQ, 256>>>(out, ln3_g, ln3_b, h);
    cudaStreamWaitEvent(0, eFC, 0);
    gemm_fp16<<<dim3(32, 64), 256, SMG>>>(
        h, 1024, w + WS_FC, 1024,
        fc_b, nullptr, nullptr, ffn, 4096, 1024, 1);
    cudaStreamWaitEvent(0, ePROJ, 0);
    gemm_fp16<<<dim3(8, 64), 256, SMG>>>(
        ffn, 4096, w + WS_PROJ, 4096,
        proj_b, out, out, nullptr, 1024, 4096, 0);
}